// round 10
// baseline (speedup 1.0000x reference)
#include <cuda_runtime.h>
#include <cuda_bf16.h>
#include <cstdint>

#define BATCH 64
#define SEQ   256
#define HID   512
#define NTAG  48
#define MROWS (BATCH*SEQ)     // 16384
#define G4    2048
#define H2    1024

typedef __nv_bfloat16 bf16;
typedef __nv_bfloat162 bf162;

// ------------------- static device scratch -------------------
__device__ bf16  d_inb[16384*256];
__device__ bf16  d_W0m[4096*256];
__device__ bf16  d_W1m[4096*1024];
__device__ bf16  d_Wh0f[2048*512];
__device__ bf16  d_Wh0b[2048*512];
__device__ bf16  d_Wh1f[2048*512];
__device__ bf16  d_Wh1b[2048*512];
__device__ float d_b0m[4096];
__device__ float d_b1m[4096];
__device__ bf16  d_fc1wP[512*1024];
__device__ float d_fc1bP[512];
__device__ bf16  d_fc2wB[256*512];
__device__ bf16  d_fc3wB[48*256];
__device__ bf16  d_pre[(size_t)16384*4096];
__device__ bf16  d_x1[16384*1024];
__device__ bf16  d_x2[16384*1024];
__device__ bf16  d_f1[16384*512];
__device__ bf16  d_f2[16384*256];
__device__ float d_em[16384*48];
__device__ bf16  d_hbuf[2*2*BATCH*HID];   // [parity][dir][b][j]
__device__ float d_v[64];
__device__ int   d_slot[2][512];          // slot ns at index ns*8 (32B stride)

// ------------------- helpers -------------------
__device__ __forceinline__ void mma16r(float* c,
    unsigned a0, unsigned a1, unsigned a2, unsigned a3, unsigned b0, unsigned b1){
    asm volatile(
        "mma.sync.aligned.m16n8k16.row.col.f32.bf16.bf16.f32 "
        "{%0,%1,%2,%3}, {%4,%5,%6,%7}, {%8,%9}, {%0,%1,%2,%3};\n"
        : "+f"(c[0]), "+f"(c[1]), "+f"(c[2]), "+f"(c[3])
        : "r"(a0), "r"(a1), "r"(a2), "r"(a3), "r"(b0), "r"(b1));
}

__device__ __forceinline__ void ldsm4(unsigned& r0, unsigned& r1, unsigned& r2, unsigned& r3,
                                      unsigned addr){
    asm volatile("ldmatrix.sync.aligned.m8n8.x4.shared.b16 {%0,%1,%2,%3}, [%4];"
        : "=r"(r0), "=r"(r1), "=r"(r2), "=r"(r3) : "r"(addr));
}

__device__ __forceinline__ float fsig(float x){
    float t;
    asm("mul.f32 %0, %1, 0fBFB8AA3B;" : "=f"(t) : "f"(x));
    asm("ex2.approx.f32 %0, %0;" : "+f"(t));
    asm("add.f32 %0, %0, 0f3F800000;" : "+f"(t));
    asm("rcp.approx.f32 %0, %0;" : "+f"(t));
    return t;
}
__device__ __forceinline__ float ftanh(float x){
    float r; asm("tanh.approx.f32 %0, %1;" : "=f"(r) : "f"(x)); return r;
}

__device__ __forceinline__ void st_release(int* addr, int v){
    asm volatile("st.release.gpu.global.s32 [%0], %1;" :: "l"(addr), "r"(v) : "memory");
}
__device__ __forceinline__ int ld_acquire(const int* addr){
    int v;
    asm volatile("ld.acquire.gpu.global.s32 %0, [%1];" : "=r"(v) : "l"(addr) : "memory");
    return v;
}

__device__ __forceinline__ void cp16(void* smem, const void* gmem){
    unsigned sa = (unsigned)__cvta_generic_to_shared(smem);
    asm volatile("cp.async.cg.shared.global [%0], [%1], 16;" :: "r"(sa), "l"(gmem));
}
__device__ __forceinline__ void cp16z(void* smem, const void* gmem, int pred){
    unsigned sa = (unsigned)__cvta_generic_to_shared(smem);
    int bytes = pred ? 16 : 0;
    asm volatile("cp.async.cg.shared.global [%0], [%1], 16, %2;" :: "r"(sa), "l"(gmem), "r"(bytes));
}
__device__ __forceinline__ void cp_commit(){ asm volatile("cp.async.commit_group;"); }
__device__ __forceinline__ void cp_wait0(){ asm volatile("cp.async.wait_group 0;"); }
__device__ __forceinline__ void cp_wait1(){ asm volatile("cp.async.wait_group 1;"); }

// ------------------- prep -------------------
// new gate permutation: permuted col p -> unit j = (p>>5)*8 + ((p>>4)&1)*4 + ((p>>1)&3),
// gate g = ((p>>3)&1)*2 + (p&1); source row = g*512 + j
__device__ __forceinline__ int perm_src(int np2){
    int j  = ((np2 >> 5) << 3) + (((np2 >> 4) & 1) << 2) + ((np2 >> 1) & 3);
    int gt = (((np2 >> 3) & 1) << 1) + (np2 & 1);
    return gt*512 + j;
}

__global__ void prep_all(
    const float* __restrict__ inputs,
    const float* __restrict__ Wih0f, const float* __restrict__ Wih0b,
    const float* __restrict__ Whh0f, const float* __restrict__ Whh0b,
    const float* __restrict__ Wih1f, const float* __restrict__ Wih1b,
    const float* __restrict__ Whh1f, const float* __restrict__ Whh1b,
    const float* __restrict__ bih0f, const float* __restrict__ bhh0f,
    const float* __restrict__ bih0b, const float* __restrict__ bhh0b,
    const float* __restrict__ bih1f, const float* __restrict__ bhh1f,
    const float* __restrict__ bih1b, const float* __restrict__ bhh1b,
    const float* __restrict__ fc2w, const float* __restrict__ fc3w)
{
    const int NIN = 16384*256;
    const int NW0 = 4096*256;
    const int NW1 = 4096*1024;
    const int NWH = 2048*512;
    const int e0 = NIN;
    const int e1 = e0 + NW0;
    const int e2 = e1 + NW1;
    const int e3 = e2 + 4*NWH;
    const int e4 = e3 + 4096;
    const int e5 = e4 + 4096;
    const int e6 = e5 + 256*512;
    const int e7 = e6 + 48*256;
    const int total = e7 + 1024;        // ctrl: 1024 slots
    int stride = gridDim.x * blockDim.x;
    for (int i = blockIdx.x*blockDim.x + threadIdx.x; i < total; i += stride){
        if (i < e0){
            d_inb[i] = __float2bfloat16_rn(inputs[i]);
        } else if (i < e1){
            int j = i - e0;
            int np = j >> 8, k = j & 255;
            int sr = perm_src(np & 2047);
            const float* src = (np < 2048) ? Wih0f : Wih0b;
            d_W0m[j] = __float2bfloat16_rn(src[sr*256 + k]);
        } else if (i < e2){
            int j = i - e1;
            int np = j >> 10, k = j & 1023;
            int sr = perm_src(np & 2047);
            const float* src = (np < 2048) ? Wih1f : Wih1b;
            d_W1m[j] = __float2bfloat16_rn(src[sr*1024 + k]);
        } else if (i < e3){
            int j = i - e2;
            int arr = j / NWH;
            int jj = j - arr*NWH;
            int np = jj >> 9, k = jj & 511;
            int sr = perm_src(np);
            const float* src = (arr==0)?Whh0f:(arr==1)?Whh0b:(arr==2)?Whh1f:Whh1b;
            bf16* dst = (arr==0)?d_Wh0f:(arr==1)?d_Wh0b:(arr==2)?d_Wh1f:d_Wh1b;
            dst[jj] = __float2bfloat16_rn(src[sr*512 + k]);
        } else if (i < e4){
            int np = i - e3;
            int sr = perm_src(np & 2047);
            d_b0m[np] = (np < 2048) ? (bih0f[sr] + bhh0f[sr]) : (bih0b[sr] + bhh0b[sr]);
        } else if (i < e5){
            int np = i - e4;
            int sr = perm_src(np & 2047);
            d_b1m[np] = (np < 2048) ? (bih1f[sr] + bhh1f[sr]) : (bih1b[sr] + bhh1b[sr]);
        } else if (i < e6){
            int j = i - e5;
            d_fc2wB[j] = __float2bfloat16_rn(fc2w[j]);
        } else if (i < e7){
            int j = i - e6;
            d_fc3wB[j] = __float2bfloat16_rn(fc3w[j]);
        } else {
            ((int*)d_slot)[i - e7] = 0;
        }
    }
}

// fold BN into fc1
__global__ void prep_fc(const float* __restrict__ fc1w, const float* __restrict__ fc1b,
                        const float* __restrict__ gamma, const float* __restrict__ beta,
                        const float* __restrict__ mean, const float* __restrict__ var)
{
    __shared__ float red[256];
    int r = blockIdx.x;
    int tid = threadIdx.x;
    float part = 0.f;
    for (int c = tid; c < 1024; c += 256){
        float sc = gamma[c] * rsqrtf(var[c] + 1e-5f);
        float tc = beta[c] - mean[c]*sc;
        float w = fc1w[r*1024 + c];
        d_fc1wP[r*1024 + c] = __float2bfloat16_rn(w * sc);
        part += w * tc;
    }
    red[tid] = part;
    __syncthreads();
    for (int off = 128; off > 0; off >>= 1){
        if (tid < off) red[tid] += red[tid + off];
        __syncthreads();
    }
    if (tid == 0) d_fc1bP[r] = fc1b[r] + red[0];
}

// ------------------- bf16 GEMM: C = A(MxK) @ W(NxK)^T + bias -------------------
#define BRS 40
__global__ __launch_bounds__(256) void gemm_bf16(
    const bf16* __restrict__ A, const bf16* __restrict__ W,
    const float* __restrict__ bias, void* __restrict__ Cv,
    int M, int N, int K, int relu, int outBf)
{
    extern __shared__ bf16 smb[];
    bf16* As = smb;
    bf16* Bs = smb + 2*128*BRS;
    int tid  = threadIdx.x;
    int warp = tid >> 5, lane = tid & 31;
    int wm = warp >> 2, wn = warp & 3;
    int g = lane >> 2, tg = lane & 3;
    int m0 = blockIdx.y*128, n0 = blockIdx.x*128;

    float acc[4][4][4];
#pragma unroll
    for (int a = 0; a < 4; a++)
#pragma unroll
        for (int b = 0; b < 4; b++)
#pragma unroll
            for (int c = 0; c < 4; c++) acc[a][b][c] = 0.f;

    int KT = K >> 5;

    auto stage = [&](int kt, int bb){
        const bf16* Ag = A + (size_t)m0*K + kt*32;
#pragma unroll
        for (int i = 0; i < 2; i++){
            int q = i*256 + tid;
            int r = q >> 2;
            int c = (q & 3) * 8;
            cp16(&As[bb*128*BRS + r*BRS + c], Ag + (size_t)r*K + c);
        }
        const bf16* Wg = W + kt*32;
#pragma unroll
        for (int i = 0; i < 2; i++){
            int q = i*256 + tid;
            int r = q >> 2;
            int c = (q & 3) * 8;
            int nr = n0 + r;
            int nc = nr < N ? nr : 0;
            cp16z(&Bs[bb*128*BRS + r*BRS + c], Wg + (size_t)nc*K + c, nr < N);
        }
        cp_commit();
    };

    stage(0, 0);
    if (KT > 1) stage(1, 1);

    for (int kt = 0; kt < KT; kt++){
        if (kt < KT-1) cp_wait1(); else cp_wait0();
        __syncthreads();
        int bb = kt & 1;
        const bf16* Ab = As + bb*128*BRS + (wm*64)*BRS;
        const bf16* Bb = Bs + bb*128*BRS + (wn*32)*BRS;
#pragma unroll
        for (int kk = 0; kk < 2; kk++){
            int kc = kk*16 + tg*2;
            unsigned af[4][4], bf[4][2];
#pragma unroll
            for (int mt = 0; mt < 4; mt++){
                const bf16* p = Ab + (mt*16 + g)*BRS + kc;
                af[mt][0] = *(const unsigned*)p;
                af[mt][1] = *(const unsigned*)(p + 8*BRS);
                af[mt][2] = *(const unsigned*)(p + 8);
                af[mt][3] = *(const unsigned*)(p + 8*BRS + 8);
            }
#pragma unroll
            for (int nt = 0; nt < 4; nt++){
                const bf16* p = Bb + (nt*8 + g)*BRS + kc;
                bf[nt][0] = *(const unsigned*)p;
                bf[nt][1] = *(const unsigned*)(p + 8);
            }
#pragma unroll
            for (int mt = 0; mt < 4; mt++)
#pragma unroll
                for (int nt = 0; nt < 4; nt++)
                    mma16r(acc[mt][nt], af[mt][0], af[mt][1], af[mt][2], af[mt][3],
                           bf[nt][0], bf[nt][1]);
        }
        __syncthreads();
        if (kt + 2 < KT) stage(kt+2, bb);
    }

#pragma unroll
    for (int mt = 0; mt < 4; mt++){
        int row = m0 + wm*64 + mt*16 + g;
#pragma unroll
        for (int nt = 0; nt < 4; nt++){
            int col = n0 + wn*32 + nt*8 + 2*tg;
            if (col < N){
                float b0 = bias[col], b1 = bias[col+1];
                float v0 = acc[mt][nt][0] + b0;
                float v1 = acc[mt][nt][1] + b1;
                float v2 = acc[mt][nt][2] + b0;
                float v3 = acc[mt][nt][3] + b1;
                if (relu){
                    v0 = fmaxf(v0, 0.f); v1 = fmaxf(v1, 0.f);
                    v2 = fmaxf(v2, 0.f); v3 = fmaxf(v3, 0.f);
                }
                if (outBf){
                    bf16* C16 = (bf16*)Cv;
                    *(bf162*)&C16[(size_t)row*N + col]     = __floats2bfloat162_rn(v0, v1);
                    *(bf162*)&C16[(size_t)(row+8)*N + col] = __floats2bfloat162_rn(v2, v3);
                } else {
                    float* C = (float*)Cv;
                    *(float2*)&C[(size_t)row*N + col]     = make_float2(v0, v1);
                    *(float2*)&C[(size_t)(row+8)*N + col] = make_float2(v2, v3);
                }
            }
        }
    }
}

// ------------------- persistent bidirectional LSTM layer -------------------
// 128 blocks x 256 threads. dir = bx>>6, ns = bx&63. Block owns permuted gate cols
// [ns*32,+32) = units [ns*8,+8). 8 warps: wm=warp>>1 (m 16 rows each), wn=warp&1 (n 16).
// Thread (g,tg) of warp holds full gates of unit wn*4+tg, rows wm*16+g and +8.
#define WSB 520
#define PSB 40
__global__ __launch_bounds__(256) void lstm_layer(
    const bf16* __restrict__ pre,
    const bf16* __restrict__ whhF, const bf16* __restrict__ whhB,
    bf16* __restrict__ out, int gen0)
{
    extern __shared__ char smraw[];
    bf16* whh_s = (bf16*)smraw;                  // [32][WSB]
    bf16* h_s   = whh_s + 32*WSB;                // [64][WSB]
    bf16* pre_s = h_s + 64*WSB;                  // [2][64][PSB]

    int tid = threadIdx.x;
    int warp = tid >> 5, lane = tid & 31;
    int wm = warp >> 1, wn = warp & 1;
    int g = lane >> 2, tg = lane & 3;
    int dir = blockIdx.x >> 6;
    int ns  = blockIdx.x & 63;
    int n0  = ns*32;
    int j0  = ns*8;
    const bf16* whh = dir ? whhB : whhF;
    int* slots = &d_slot[dir][0];

    // persistent Whh slice: 32 permuted gate rows x 512
#pragma unroll
    for (int i = 0; i < 8; i++){
        int q = i*256 + tid;
        int r = q >> 6;
        int c = (q & 63) * 8;
        cp16(&whh_s[r*WSB + c], &whh[(n0 + r)*512 + c]);
    }
    cp_commit();

    // ldmatrix lane addresses
    int lrow = lane & 15;
    int lcol = (lane >> 4) * 16;
    unsigned hbase = (unsigned)__cvta_generic_to_shared(h_s);
    unsigned wbase = (unsigned)__cvta_generic_to_shared(whh_s);
    unsigned aAddr = hbase + (unsigned)((wm*16 + lrow)*WSB)*2u + lcol;
    unsigned bAddr = wbase + (unsigned)((wn*16 + lrow)*WSB)*2u + lcol;

    // gate-phase coords
    int rrA = wm*16 + g;
    int rrB = rrA + 8;
    int un  = wn*4 + tg;
    int pcI = wn*16 + 2*tg;       // i,f pair col within pre_s row

    // h-fetch slice coords
    int sn = tid >> 2;            // producer slice 0..63
    int r4 = (tid & 3) * 16;      // first of 16 rows

    // pre staging coords
    int pr_ = tid >> 2, pc_ = (tid & 3)*8;

    float cA = 0.f, cB = 0.f;

    cp_wait0();
    __syncthreads();

    // prefetch pre for step 0 (group P_{-1})
    {
        int t0 = dir ? (SEQ-1) : 0;
        cp16(&pre_s[pr_*PSB + pc_], &pre[((size_t)(pr_*SEQ + t0))*4096 + dir*2048 + n0 + pc_]);
        cp_commit();
    }

    for (int s = 0; s < SEQ; s++){
        int t  = dir ? (SEQ-1 - s) : s;
        int rp = s & 1;
        int wp = rp ^ 1;

        // per-producer poll + slice fetch (group H_s)
        if (s > 0){
            int need = gen0 + s;
            const bf16* hsrc = d_hbuf + (size_t)(rp*2 + dir)*BATCH*HID;
            while (ld_acquire(&slots[sn*8]) < need) { }
            const bf16* srcc = hsrc + sn*8;
            bf16* dstc = h_s + sn*8;
#pragma unroll
            for (int r = 0; r < 16; r++)
                cp16(&dstc[(size_t)(r4 + r)*WSB], &srcc[(size_t)(r4 + r)*HID]);
        }
        cp_commit();
        // prefetch pre for step s+1 (group P_s)
        if (s + 1 < SEQ){
            int tn = dir ? (SEQ-2 - s) : (s + 1);
            bf16* pb = pre_s + ((s+1) & 1)*64*PSB;
            cp16(&pb[pr_*PSB + pc_], &pre[((size_t)(pr_*SEQ + tn))*4096 + dir*2048 + n0 + pc_]);
        }
        cp_commit();
        cp_wait1();              // H_s (+older) done; P_s may pend
        __syncthreads();

        float acc[2][4];
#pragma unroll
        for (int b = 0; b < 2; b++)
#pragma unroll
            for (int c = 0; c < 4; c++) acc[b][c] = 0.f;

        if (s > 0){
#pragma unroll 8
            for (int k16 = 0; k16 < 32; k16++){
                unsigned off = (unsigned)k16 * 32u;
                unsigned a0,a1,a2,a3, b0,b1,b2,b3;
                ldsm4(a0,a1,a2,a3, aAddr + off);
                ldsm4(b0,b1,b2,b3, bAddr + off);
                mma16r(acc[0], a0,a1,a2,a3, b0,b2);
                mma16r(acc[1], a0,a1,a2,a3, b1,b3);
            }
        }

        // in-register gate update: thread owns unit un, rows rrA/rrB, full gates
        bf16 hAb, hBb;
        {
            const bf16* pcur = pre_s + (s & 1)*64*PSB;
            bf162 pIFA = *(const bf162*)&pcur[rrA*PSB + pcI];
            bf162 pGOA = *(const bf162*)&pcur[rrA*PSB + pcI + 8];
            bf162 pIFB = *(const bf162*)&pcur[rrB*PSB + pcI];
            bf162 pGOB = *(const bf162*)&pcur[rrB*PSB + pcI + 8];

            float iA = acc[0][0] + __low2float(pIFA);
            float fA = acc[0][1] + __high2float(pIFA);
            float gA = acc[1][0] + __low2float(pGOA);
            float oA = acc[1][1] + __high2float(pGOA);
            cA = fsig(fA)*cA + fsig(iA)*ftanh(gA);
            float hA = fsig(oA)*ftanh(cA);

            float iB = acc[0][2] + __low2float(pIFB);
            float fB = acc[0][3] + __high2float(pIFB);
            float gB = acc[1][2] + __low2float(pGOB);
            float oB = acc[1][3] + __high2float(pGOB);
            cB = fsig(fB)*cB + fsig(iB)*ftanh(gB);
            float hB = fsig(oB)*ftanh(cB);

            hAb = __float2bfloat16_rn(hA);
            hBb = __float2bfloat16_rn(hB);
            bf16* hdst = d_hbuf + (size_t)(wp*2 + dir)*BATCH*HID;
            hdst[rrA*HID + j0 + un] = hAb;
            hdst[rrB*HID + j0 + un] = hBb;
        }

        // release after all h stores; out stores overlap next-step polling
        __syncthreads();
        if (tid == 0) st_release(&slots[ns*8], gen0 + s + 1);
        out[(size_t)(rrA*SEQ + t)*H2 + dir*HID + j0 + un] = hAb;
        out[(size_t)(rrB*SEQ + t)*H2 + dir*HID + j0 + un] = hBb;
    }
}

// ------------------- CRF: alpha' = m + log(exp(alpha-m) @ exp(T)) + em -------------------
__global__ void crf_kernel(const float* __restrict__ em, const int* __restrict__ tags,
                           const float* __restrict__ start, const float* __restrict__ endv,
                           const float* __restrict__ trans, float* __restrict__ v)
{
    __shared__ float E[NTAG*49];     // exp(trans)
    __shared__ float al[NTAG];
    __shared__ float p[NTAG];
    __shared__ float red[64];
    __shared__ float num_s;
    int b = blockIdx.x;
    int tid = threadIdx.x;
    const int* tg = tags + b*SEQ;
    const float* eb = em + b*SEQ*NTAG;

    for (int q = tid; q < NTAG*NTAG; q += 64){
        int i = q / NTAG, j = q - i*NTAG;
        E[i*49 + j] = __expf(trans[q]);
    }
    float part = 0.f;
    for (int t = tid; t < SEQ; t += 64){
        int tt = tg[t];
        part += eb[t*NTAG + tt];
        if (t < SEQ-1) part += trans[tt*NTAG + tg[t+1]];
    }
    red[tid] = part;
    if (tid < NTAG) al[tid] = start[tid] + eb[tid];
    __syncthreads();
    if (tid == 0){
        float s = 0.f;
        for (int i = 0; i < 64; i++) s += red[i];
        num_s = s + start[tg[0]] + endv[tg[SEQ-1]];
    }
    __syncthreads();

    for (int t = 1; t < SEQ; t++){
        if (tid < NTAG) p[tid] = __expf(al[tid] - al[0]);
        __syncthreads();
        float na = 0.f;
        if (tid < NTAG){
            float m0 = al[0];
            float ssum = 0.f;
#pragma unroll 8
            for (int i = 0; i < NTAG; i++) ssum += p[i] * E[i*49 + tid];
            na = m0 + __logf(ssum) + eb[t*NTAG + tid];
        }
        __syncthreads();
        if (tid < NTAG) al[tid] = na;
        __syncthreads();
    }

    if (tid == 0){
        float m = -1e30f;
        for (int j = 0; j < NTAG; j++) m = fmaxf(m, al[j] + endv[j]);
        float s = 0.f;
        for (int j = 0; j < NTAG; j++) s += __expf(al[j] + endv[j] - m);
        v[b] = num_s - (m + __logf(s));
    }
}

__global__ void final_reduce(const float* __restrict__ v, float* __restrict__ out){
    __shared__ float s[64];
    s[threadIdx.x] = v[threadIdx.x];
    __syncthreads();
    if (threadIdx.x == 0){
        float a = 0.f;
        for (int i = 0; i < 64; i++) a += s[i];
        out[0] = -(a / 64.f);
    }
}

// ------------------- launch -------------------
extern "C" void kernel_launch(void* const* d_in, const int* in_sizes, int n_in,
                              void* d_out, int out_size)
{
    const float* inputs = (const float*)d_in[0];
    const int*   tags   = (const int*)d_in[1];
    const float *Wih0f=(const float*)d_in[2],  *Whh0f=(const float*)d_in[3],
                *bih0f=(const float*)d_in[4],  *bhh0f=(const float*)d_in[5];
    const float *Wih0b=(const float*)d_in[6],  *Whh0b=(const float*)d_in[7],
                *bih0b=(const float*)d_in[8],  *bhh0b=(const float*)d_in[9];
    const float *Wih1f=(const float*)d_in[10], *Whh1f=(const float*)d_in[11],
                *bih1f=(const float*)d_in[12], *bhh1f=(const float*)d_in[13];
    const float *Wih1b=(const float*)d_in[14], *Whh1b=(const float*)d_in[15],
                *bih1b=(const float*)d_in[16], *bhh1b=(const float*)d_in[17];
    const float *gamma=(const float*)d_in[18], *beta=(const float*)d_in[19],
                *mean=(const float*)d_in[20],  *var=(const float*)d_in[21];
    const float *fc1w=(const float*)d_in[22], *fc1b=(const float*)d_in[23];
    const float *fc2w=(const float*)d_in[24], *fc2b=(const float*)d_in[25];
    const float *fc3w=(const float*)d_in[26], *fc3b=(const float*)d_in[27];
    const float *crfS=(const float*)d_in[28], *crfE=(const float*)d_in[29],
                *crfT=(const float*)d_in[30];

    bf16 *pInb,*pW0m,*pW1m,*pWh0f,*pWh0b,*pWh1f,*pWh1b;
    bf16 *pFc1w,*pFc2w,*pFc3w,*pX1,*pX2,*pF1,*pF2,*pPre;
    float *pB0m,*pB1m,*pFc1b,*pEm,*pV;
    cudaGetSymbolAddress((void**)&pInb, d_inb);
    cudaGetSymbolAddress((void**)&pW0m, d_W0m);
    cudaGetSymbolAddress((void**)&pW1m, d_W1m);
    cudaGetSymbolAddress((void**)&pWh0f, d_Wh0f);
    cudaGetSymbolAddress((void**)&pWh0b, d_Wh0b);
    cudaGetSymbolAddress((void**)&pWh1f, d_Wh1f);
    cudaGetSymbolAddress((void**)&pWh1b, d_Wh1b);
    cudaGetSymbolAddress((void**)&pB0m, d_b0m);
    cudaGetSymbolAddress((void**)&pB1m, d_b1m);
    cudaGetSymbolAddress((void**)&pFc1w, d_fc1wP);
    cudaGetSymbolAddress((void**)&pFc1b, d_fc1bP);
    cudaGetSymbolAddress((void**)&pFc2w, d_fc2wB);
    cudaGetSymbolAddress((void**)&pFc3w, d_fc3wB);
    cudaGetSymbolAddress((void**)&pPre, d_pre);
    cudaGetSymbolAddress((void**)&pX1, d_x1);
    cudaGetSymbolAddress((void**)&pX2, d_x2);
    cudaGetSymbolAddress((void**)&pF1, d_f1);
    cudaGetSymbolAddress((void**)&pF2, d_f2);
    cudaGetSymbolAddress((void**)&pEm, d_em);
    cudaGetSymbolAddress((void**)&pV, d_v);

    const int gemm_smem = 2*2*128*BRS*2;
    const int lstm_smem = (32*WSB + 64*WSB + 2*64*PSB)*2;
    cudaFuncSetAttribute(gemm_bf16, cudaFuncAttributeMaxDynamicSharedMemorySize, gemm_smem);
    cudaFuncSetAttribute(lstm_layer, cudaFuncAttributeMaxDynamicSharedMemorySize, lstm_smem);

    prep_all<<<2048,256>>>(inputs, Wih0f, Wih0b, Whh0f, Whh0b, Wih1f, Wih1b, Whh1f, Whh1b,
                           bih0f, bhh0f, bih0b, bhh0b, bih1f, bhh1f, bih1b, bhh1b,
                           fc2w, fc3w);
    prep_fc<<<512,256>>>(fc1w, fc1b, gamma, beta, mean, var);
    gemm_bf16<<<dim3(32,128),256,gemm_smem>>>(pInb, pW0m, pB0m, pPre, MROWS, 4096, 256, 0, 1);
    lstm_layer<<<128,256,lstm_smem>>>(pPre, pWh0f, pWh0b, pX1, 0);
    gemm_bf16<<<dim3(32,128),256,gemm_smem>>>(pX1, pW1m, pB1m, pPre, MROWS, 4096, 1024, 0, 1);
    lstm_layer<<<128,256,lstm_smem>>>(pPre, pWh1f, pWh1b, pX2, 256);
    gemm_bf16<<<dim3(4,128),256,gemm_smem>>>(pX2, pFc1w, pFc1b, pF1, MROWS, 512, 1024, 1, 1);
    gemm_bf16<<<dim3(2,128),256,gemm_smem>>>(pF1, pFc2w, fc2b, pF2, MROWS, 256, 512, 1, 1);
    gemm_bf16<<<dim3(1,128),256,gemm_smem>>>(pF2, pFc3w, fc3b, pEm, MROWS, NTAG, 256, 0, 0);
    crf_kernel<<<64,64>>>(pEm, tags, crfS, crfE, crfT, pV);
    final_reduce<<<1,64>>>(pV, (float*)d_out);
}

// round 11
// speedup vs baseline: 1.3019x; 1.3019x over previous
#include <cuda_runtime.h>
#include <cuda_bf16.h>
#include <cstdint>

#define BATCH 64
#define SEQ   256
#define HID   512
#define NTAG  48
#define MROWS (BATCH*SEQ)     // 16384
#define G4    2048
#define H2    1024

typedef __nv_bfloat16 bf16;
typedef __nv_bfloat162 bf162;

// ------------------- static device scratch -------------------
__device__ bf16  d_inb[16384*256];
__device__ bf16  d_W0m[4096*256];
__device__ bf16  d_W1m[4096*1024];
__device__ bf16  d_Wh0f[2048*512];
__device__ bf16  d_Wh0b[2048*512];
__device__ bf16  d_Wh1f[2048*512];
__device__ bf16  d_Wh1b[2048*512];
__device__ float d_b0m[4096];
__device__ float d_b1m[4096];
__device__ bf16  d_fc1wP[512*1024];
__device__ float d_fc1bP[512];
__device__ bf16  d_fc2wB[256*512];
__device__ bf16  d_fc3wB[48*256];
__device__ bf16  d_pre[(size_t)16384*4096];
__device__ bf16  d_x1[16384*1024];
__device__ bf16  d_x2[16384*1024];
__device__ bf16  d_f1[16384*512];
__device__ bf16  d_f2[16384*256];
__device__ float d_em[16384*48];
__device__ bf16  d_hbuf[2*2*BATCH*HID];   // [parity][dir][b][j]
__device__ float d_v[64];
__device__ int   d_slot[2][512];          // slot ns at index ns*8 (32B stride)

// ------------------- helpers -------------------
__device__ __forceinline__ void mma16r(float* c,
    unsigned a0, unsigned a1, unsigned a2, unsigned a3, unsigned b0, unsigned b1){
    asm volatile(
        "mma.sync.aligned.m16n8k16.row.col.f32.bf16.bf16.f32 "
        "{%0,%1,%2,%3}, {%4,%5,%6,%7}, {%8,%9}, {%0,%1,%2,%3};\n"
        : "+f"(c[0]), "+f"(c[1]), "+f"(c[2]), "+f"(c[3])
        : "r"(a0), "r"(a1), "r"(a2), "r"(a3), "r"(b0), "r"(b1));
}

__device__ __forceinline__ void ldsm4(unsigned& r0, unsigned& r1, unsigned& r2, unsigned& r3,
                                      unsigned addr){
    asm volatile("ldmatrix.sync.aligned.m8n8.x4.shared.b16 {%0,%1,%2,%3}, [%4];"
        : "=r"(r0), "=r"(r1), "=r"(r2), "=r"(r3) : "r"(addr));
}

__device__ __forceinline__ float fsig(float x){
    float t;
    asm("mul.f32 %0, %1, 0fBFB8AA3B;" : "=f"(t) : "f"(x));
    asm("ex2.approx.f32 %0, %0;" : "+f"(t));
    asm("add.f32 %0, %0, 0f3F800000;" : "+f"(t));
    asm("rcp.approx.f32 %0, %0;" : "+f"(t));
    return t;
}
__device__ __forceinline__ float ftanh(float x){
    float r; asm("tanh.approx.f32 %0, %1;" : "=f"(r) : "f"(x)); return r;
}

__device__ __forceinline__ void st_release(int* addr, int v){
    asm volatile("st.release.gpu.global.s32 [%0], %1;" :: "l"(addr), "r"(v) : "memory");
}
__device__ __forceinline__ int ld_acquire(const int* addr){
    int v;
    asm volatile("ld.acquire.gpu.global.s32 %0, [%1];" : "=r"(v) : "l"(addr) : "memory");
    return v;
}

__device__ __forceinline__ void cp16(void* smem, const void* gmem){
    unsigned sa = (unsigned)__cvta_generic_to_shared(smem);
    asm volatile("cp.async.cg.shared.global [%0], [%1], 16;" :: "r"(sa), "l"(gmem));
}
__device__ __forceinline__ void cp16z(void* smem, const void* gmem, int pred){
    unsigned sa = (unsigned)__cvta_generic_to_shared(smem);
    int bytes = pred ? 16 : 0;
    asm volatile("cp.async.cg.shared.global [%0], [%1], 16, %2;" :: "r"(sa), "l"(gmem), "r"(bytes));
}
__device__ __forceinline__ void cp_commit(){ asm volatile("cp.async.commit_group;"); }
__device__ __forceinline__ void cp_wait0(){ asm volatile("cp.async.wait_group 0;"); }
__device__ __forceinline__ void cp_wait1(){ asm volatile("cp.async.wait_group 1;"); }
__device__ __forceinline__ void cp_wait2(){ asm volatile("cp.async.wait_group 2;"); }

// ------------------- prep -------------------
// gate permutation: permuted col p -> unit j = (p>>5)*8 + ((p>>4)&1)*4 + ((p>>1)&3),
// gate g = ((p>>3)&1)*2 + (p&1); source row = g*512 + j
__device__ __forceinline__ int perm_src(int np2){
    int j  = ((np2 >> 5) << 3) + (((np2 >> 4) & 1) << 2) + ((np2 >> 1) & 3);
    int gt = (((np2 >> 3) & 1) << 1) + (np2 & 1);
    return gt*512 + j;
}

__global__ void prep_all(
    const float* __restrict__ inputs,
    const float* __restrict__ Wih0f, const float* __restrict__ Wih0b,
    const float* __restrict__ Whh0f, const float* __restrict__ Whh0b,
    const float* __restrict__ Wih1f, const float* __restrict__ Wih1b,
    const float* __restrict__ Whh1f, const float* __restrict__ Whh1b,
    const float* __restrict__ bih0f, const float* __restrict__ bhh0f,
    const float* __restrict__ bih0b, const float* __restrict__ bhh0b,
    const float* __restrict__ bih1f, const float* __restrict__ bhh1f,
    const float* __restrict__ bih1b, const float* __restrict__ bhh1b,
    const float* __restrict__ fc2w, const float* __restrict__ fc3w)
{
    const int NIN = 16384*256;
    const int NW0 = 4096*256;
    const int NW1 = 4096*1024;
    const int NWH = 2048*512;
    const int e0 = NIN;
    const int e1 = e0 + NW0;
    const int e2 = e1 + NW1;
    const int e3 = e2 + 4*NWH;
    const int e4 = e3 + 4096;
    const int e5 = e4 + 4096;
    const int e6 = e5 + 256*512;
    const int e7 = e6 + 48*256;
    const int total = e7 + 1024;
    int stride = gridDim.x * blockDim.x;
    for (int i = blockIdx.x*blockDim.x + threadIdx.x; i < total; i += stride){
        if (i < e0){
            d_inb[i] = __float2bfloat16_rn(inputs[i]);
        } else if (i < e1){
            int j = i - e0;
            int np = j >> 8, k = j & 255;
            int sr = perm_src(np & 2047);
            const float* src = (np < 2048) ? Wih0f : Wih0b;
            d_W0m[j] = __float2bfloat16_rn(src[sr*256 + k]);
        } else if (i < e2){
            int j = i - e1;
            int np = j >> 10, k = j & 1023;
            int sr = perm_src(np & 2047);
            const float* src = (np < 2048) ? Wih1f : Wih1b;
            d_W1m[j] = __float2bfloat16_rn(src[sr*1024 + k]);
        } else if (i < e3){
            int j = i - e2;
            int arr = j / NWH;
            int jj = j - arr*NWH;
            int np = jj >> 9, k = jj & 511;
            int sr = perm_src(np);
            const float* src = (arr==0)?Whh0f:(arr==1)?Whh0b:(arr==2)?Whh1f:Whh1b;
            bf16* dst = (arr==0)?d_Wh0f:(arr==1)?d_Wh0b:(arr==2)?d_Wh1f:d_Wh1b;
            dst[jj] = __float2bfloat16_rn(src[sr*512 + k]);
        } else if (i < e4){
            int np = i - e3;
            int sr = perm_src(np & 2047);
            d_b0m[np] = (np < 2048) ? (bih0f[sr] + bhh0f[sr]) : (bih0b[sr] + bhh0b[sr]);
        } else if (i < e5){
            int np = i - e4;
            int sr = perm_src(np & 2047);
            d_b1m[np] = (np < 2048) ? (bih1f[sr] + bhh1f[sr]) : (bih1b[sr] + bhh1b[sr]);
        } else if (i < e6){
            int j = i - e5;
            d_fc2wB[j] = __float2bfloat16_rn(fc2w[j]);
        } else if (i < e7){
            int j = i - e6;
            d_fc3wB[j] = __float2bfloat16_rn(fc3w[j]);
        } else {
            ((int*)d_slot)[i - e7] = 0;
        }
    }
}

// fold BN into fc1
__global__ void prep_fc(const float* __restrict__ fc1w, const float* __restrict__ fc1b,
                        const float* __restrict__ gamma, const float* __restrict__ beta,
                        const float* __restrict__ mean, const float* __restrict__ var)
{
    __shared__ float red[256];
    int r = blockIdx.x;
    int tid = threadIdx.x;
    float part = 0.f;
    for (int c = tid; c < 1024; c += 256){
        float sc = gamma[c] * rsqrtf(var[c] + 1e-5f);
        float tc = beta[c] - mean[c]*sc;
        float w = fc1w[r*1024 + c];
        d_fc1wP[r*1024 + c] = __float2bfloat16_rn(w * sc);
        part += w * tc;
    }
    red[tid] = part;
    __syncthreads();
    for (int off = 128; off > 0; off >>= 1){
        if (tid < off) red[tid] += red[tid + off];
        __syncthreads();
    }
    if (tid == 0) d_fc1bP[r] = fc1b[r] + red[0];
}

// ------------------- bf16 GEMM: C = A(MxK) @ W(NxK)^T + bias -------------------
#define BRS 40
__global__ __launch_bounds__(256) void gemm_bf16(
    const bf16* __restrict__ A, const bf16* __restrict__ W,
    const float* __restrict__ bias, void* __restrict__ Cv,
    int M, int N, int K, int relu, int outBf)
{
    extern __shared__ bf16 smb[];
    bf16* As = smb;
    bf16* Bs = smb + 2*128*BRS;
    int tid  = threadIdx.x;
    int warp = tid >> 5, lane = tid & 31;
    int wm = warp >> 2, wn = warp & 3;
    int g = lane >> 2, tg = lane & 3;
    int m0 = blockIdx.y*128, n0 = blockIdx.x*128;

    float acc[4][4][4];
#pragma unroll
    for (int a = 0; a < 4; a++)
#pragma unroll
        for (int b = 0; b < 4; b++)
#pragma unroll
            for (int c = 0; c < 4; c++) acc[a][b][c] = 0.f;

    int KT = K >> 5;

    auto stage = [&](int kt, int bb){
        const bf16* Ag = A + (size_t)m0*K + kt*32;
#pragma unroll
        for (int i = 0; i < 2; i++){
            int q = i*256 + tid;
            int r = q >> 2;
            int c = (q & 3) * 8;
            cp16(&As[bb*128*BRS + r*BRS + c], Ag + (size_t)r*K + c);
        }
        const bf16* Wg = W + kt*32;
#pragma unroll
        for (int i = 0; i < 2; i++){
            int q = i*256 + tid;
            int r = q >> 2;
            int c = (q & 3) * 8;
            int nr = n0 + r;
            int nc = nr < N ? nr : 0;
            cp16z(&Bs[bb*128*BRS + r*BRS + c], Wg + (size_t)nc*K + c, nr < N);
        }
        cp_commit();
    };

    stage(0, 0);
    if (KT > 1) stage(1, 1);

    for (int kt = 0; kt < KT; kt++){
        if (kt < KT-1) cp_wait1(); else cp_wait0();
        __syncthreads();
        int bb = kt & 1;
        const bf16* Ab = As + bb*128*BRS + (wm*64)*BRS;
        const bf16* Bb = Bs + bb*128*BRS + (wn*32)*BRS;
#pragma unroll
        for (int kk = 0; kk < 2; kk++){
            int kc = kk*16 + tg*2;
            unsigned af[4][4], bf[4][2];
#pragma unroll
            for (int mt = 0; mt < 4; mt++){
                const bf16* p = Ab + (mt*16 + g)*BRS + kc;
                af[mt][0] = *(const unsigned*)p;
                af[mt][1] = *(const unsigned*)(p + 8*BRS);
                af[mt][2] = *(const unsigned*)(p + 8);
                af[mt][3] = *(const unsigned*)(p + 8*BRS + 8);
            }
#pragma unroll
            for (int nt = 0; nt < 4; nt++){
                const bf16* p = Bb + (nt*8 + g)*BRS + kc;
                bf[nt][0] = *(const unsigned*)p;
                bf[nt][1] = *(const unsigned*)(p + 8);
            }
#pragma unroll
            for (int mt = 0; mt < 4; mt++)
#pragma unroll
                for (int nt = 0; nt < 4; nt++)
                    mma16r(acc[mt][nt], af[mt][0], af[mt][1], af[mt][2], af[mt][3],
                           bf[nt][0], bf[nt][1]);
        }
        __syncthreads();
        if (kt + 2 < KT) stage(kt+2, bb);
    }

#pragma unroll
    for (int mt = 0; mt < 4; mt++){
        int row = m0 + wm*64 + mt*16 + g;
#pragma unroll
        for (int nt = 0; nt < 4; nt++){
            int col = n0 + wn*32 + nt*8 + 2*tg;
            if (col < N){
                float b0 = bias[col], b1 = bias[col+1];
                float v0 = acc[mt][nt][0] + b0;
                float v1 = acc[mt][nt][1] + b1;
                float v2 = acc[mt][nt][2] + b0;
                float v3 = acc[mt][nt][3] + b1;
                if (relu){
                    v0 = fmaxf(v0, 0.f); v1 = fmaxf(v1, 0.f);
                    v2 = fmaxf(v2, 0.f); v3 = fmaxf(v3, 0.f);
                }
                if (outBf){
                    bf16* C16 = (bf16*)Cv;
                    *(bf162*)&C16[(size_t)row*N + col]     = __floats2bfloat162_rn(v0, v1);
                    *(bf162*)&C16[(size_t)(row+8)*N + col] = __floats2bfloat162_rn(v2, v3);
                } else {
                    float* C = (float*)Cv;
                    *(float2*)&C[(size_t)row*N + col]     = make_float2(v0, v1);
                    *(float2*)&C[(size_t)(row+8)*N + col] = make_float2(v2, v3);
                }
            }
        }
    }
}

// ------------------- persistent bidirectional LSTM layer -------------------
// 128 blocks x 256 threads. dir = bx>>6, ns = bx&63. Block owns permuted gate cols
// [ns*32,+32) = units [ns*8,+8). 8 warps: wm=warp>>1 (4 m-tiles of 16), wn=warp&1.
// Thread (g,tg) holds full i/f/g/o of unit wn*4+tg for rows wm*16+g and +8.
#define WSB 520
#define PSB 40
__global__ __launch_bounds__(256) void lstm_layer(
    const bf16* __restrict__ pre,
    const bf16* __restrict__ whhF, const bf16* __restrict__ whhB,
    bf16* __restrict__ out, int gen0)
{
    extern __shared__ char smraw[];
    bf16* whh_s = (bf16*)smraw;                  // [32][WSB]
    bf16* h_s   = whh_s + 32*WSB;                // [64][WSB]
    bf16* pre_s = h_s + 64*WSB;                  // [2][64][PSB]

    int tid = threadIdx.x;
    int warp = tid >> 5, lane = tid & 31;
    int wm = warp >> 1, wn = warp & 1;
    int g = lane >> 2, tg = lane & 3;
    int dir = blockIdx.x >> 6;
    int ns  = blockIdx.x & 63;
    int n0  = ns*32;
    int j0  = ns*8;
    const bf16* whh = dir ? whhB : whhF;
    int* slots = &d_slot[dir][0];

    // persistent Whh slice: 32 permuted gate rows x 512
#pragma unroll
    for (int i = 0; i < 8; i++){
        int q = i*256 + tid;
        int r = q >> 6;
        int c = (q & 63) * 8;
        cp16(&whh_s[r*WSB + c], &whh[(n0 + r)*512 + c]);
    }
    cp_commit();

    // ldmatrix lane addresses
    int lrow = lane & 15;
    int lcol = (lane >> 4) * 16;
    unsigned hbase = (unsigned)__cvta_generic_to_shared(h_s);
    unsigned wbase = (unsigned)__cvta_generic_to_shared(whh_s);
    unsigned aAddr = hbase + (unsigned)((wm*16 + lrow)*WSB)*2u + lcol;
    unsigned bAddr = wbase + (unsigned)((wn*16 + lrow)*WSB)*2u + lcol;

    // gate-phase coords
    int rrA = wm*16 + g;
    int rrB = rrA + 8;
    int un  = wn*4 + tg;
    int pcI = wn*16 + 2*tg;       // i,f pair col within pre_s row

    // pre staging coords
    int pr_ = tid >> 2, pc_ = (tid & 3)*8;

    float cA = 0.f, cB = 0.f;

    cp_wait0();
    __syncthreads();

    // prefetch pre for step 0 (group P_{-1})
    {
        int t0 = dir ? (SEQ-1) : 0;
        cp16(&pre_s[pr_*PSB + pc_], &pre[((size_t)(pr_*SEQ + t0))*4096 + dir*2048 + n0 + pc_]);
        cp_commit();
    }

    for (int s = 0; s < SEQ; s++){
        int t  = dir ? (SEQ-1 - s) : s;
        int rp = s & 1;
        int wp = rp ^ 1;

        // coalesced h staging: 2 chunks (k [0,256) and [256,512))
        if (s > 0){
            const bf16* hsrc = d_hbuf + (size_t)(rp*2 + dir)*BATCH*HID;
#pragma unroll
            for (int i = 0; i < 8; i++){
                int q = i*256 + tid;
                int r = q >> 5;
                int c = (q & 31) * 8;
                cp16(&h_s[r*WSB + c], &hsrc[r*HID + c]);
            }
            cp_commit();
#pragma unroll
            for (int i = 0; i < 8; i++){
                int q = i*256 + tid;
                int r = q >> 5;
                int c = (q & 31) * 8 + 256;
                cp16(&h_s[r*WSB + c], &hsrc[r*HID + c]);
            }
            cp_commit();
        }
        // prefetch pre for step s+1
        if (s + 1 < SEQ){
            int tn = dir ? (SEQ-2 - s) : (s + 1);
            bf16* pb = pre_s + ((s+1) & 1)*64*PSB;
            cp16(&pb[pr_*PSB + pc_], &pre[((size_t)(pr_*SEQ + tn))*4096 + dir*2048 + n0 + pc_]);
        }
        cp_commit();

        float acc[2][4];
#pragma unroll
        for (int b = 0; b < 2; b++)
#pragma unroll
            for (int c = 0; c < 4; c++) acc[b][c] = 0.f;

        if (s > 0){
            cp_wait2();             // h chunk0 ready (and pre(s))
            __syncthreads();
#pragma unroll 8
            for (int k16 = 0; k16 < 16; k16++){
                unsigned off = (unsigned)k16 * 32u;
                unsigned a0,a1,a2,a3, b0,b1,b2,b3;
                ldsm4(a0,a1,a2,a3, aAddr + off);
                ldsm4(b0,b1,b2,b3, bAddr + off);
                mma16r(acc[0], a0,a1,a2,a3, b0,b2);
                mma16r(acc[1], a0,a1,a2,a3, b1,b3);
            }
            cp_wait1();             // h chunk1 ready
            __syncthreads();
#pragma unroll 8
            for (int k16 = 16; k16 < 32; k16++){
                unsigned off = (unsigned)k16 * 32u;
                unsigned a0,a1,a2,a3, b0,b1,b2,b3;
                ldsm4(a0,a1,a2,a3, aAddr + off);
                ldsm4(b0,b1,b2,b3, bAddr + off);
                mma16r(acc[0], a0,a1,a2,a3, b0,b2);
                mma16r(acc[1], a0,a1,a2,a3, b1,b3);
            }
        } else {
            cp_wait1();             // pre(0) ready
            __syncthreads();
        }

        // in-register gate update: thread owns unit un, rows rrA/rrB, full gates
        bf16 hAb, hBb;
        {
            const bf16* pcur = pre_s + (s & 1)*64*PSB;
            bf162 pIFA = *(const bf162*)&pcur[rrA*PSB + pcI];
            bf162 pGOA = *(const bf162*)&pcur[rrA*PSB + pcI + 8];
            bf162 pIFB = *(const bf162*)&pcur[rrB*PSB + pcI];
            bf162 pGOB = *(const bf162*)&pcur[rrB*PSB + pcI + 8];

            float iA = acc[0][0] + __low2float(pIFA);
            float fA = acc[0][1] + __high2float(pIFA);
            float gA = acc[1][0] + __low2float(pGOA);
            float oA = acc[1][1] + __high2float(pGOA);
            cA = fsig(fA)*cA + fsig(iA)*ftanh(gA);
            float hA = fsig(oA)*ftanh(cA);

            float iB = acc[0][2] + __low2float(pIFB);
            float fB = acc[0][3] + __high2float(pIFB);
            float gB = acc[1][2] + __low2float(pGOB);
            float oB = acc[1][3] + __high2float(pGOB);
            cB = fsig(fB)*cB + fsig(iB)*ftanh(gB);
            float hB = fsig(oB)*ftanh(cB);

            hAb = __float2bfloat16_rn(hA);
            hBb = __float2bfloat16_rn(hB);
            bf16* hdst = d_hbuf + (size_t)(wp*2 + dir)*BATCH*HID;
            hdst[rrA*HID + j0 + un] = hAb;
            hdst[rrB*HID + j0 + un] = hBb;
        }

        // one-hop barrier: release -> out stores overlap -> 2-warp poll
        __syncthreads();
        int target = gen0 + s + 1;
        if (tid == 0) st_release(&slots[ns*8], target);
        out[(size_t)(rrA*SEQ + t)*H2 + dir*HID + j0 + un] = hAb;
        out[(size_t)(rrB*SEQ + t)*H2 + dir*HID + j0 + un] = hBb;
        if (tid < 64){
            while (ld_acquire(&slots[tid*8]) < target) { }
        }
        __syncthreads();
    }
}

// ------------------- CRF: alpha' = m + log(exp(alpha-m) @ exp(T)) + em -------------------
__global__ void crf_kernel(const float* __restrict__ em, const int* __restrict__ tags,
                           const float* __restrict__ start, const float* __restrict__ endv,
                           const float* __restrict__ trans, float* __restrict__ v)
{
    __shared__ float E[NTAG*49];
    __shared__ float al[NTAG];
    __shared__ float p[NTAG];
    __shared__ float red[64];
    __shared__ float num_s;
    int b = blockIdx.x;
    int tid = threadIdx.x;
    const int* tg = tags + b*SEQ;
    const float* eb = em + b*SEQ*NTAG;

    for (int q = tid; q < NTAG*NTAG; q += 64){
        int i = q / NTAG, j = q - i*NTAG;
        E[i*49 + j] = __expf(trans[q]);
    }
    float part = 0.f;
    for (int t = tid; t < SEQ; t += 64){
        int tt = tg[t];
        part += eb[t*NTAG + tt];
        if (t < SEQ-1) part += trans[tt*NTAG + tg[t+1]];
    }
    red[tid] = part;
    if (tid < NTAG) al[tid] = start[tid] + eb[tid];
    __syncthreads();
    if (tid == 0){
        float s = 0.f;
        for (int i = 0; i < 64; i++) s += red[i];
        num_s = s + start[tg[0]] + endv[tg[SEQ-1]];
    }
    __syncthreads();

    for (int t = 1; t < SEQ; t++){
        if (tid < NTAG) p[tid] = __expf(al[tid] - al[0]);
        __syncthreads();
        float na = 0.f;
        if (tid < NTAG){
            float m0 = al[0];
            float ssum = 0.f;
#pragma unroll 8
            for (int i = 0; i < NTAG; i++) ssum += p[i] * E[i*49 + tid];
            na = m0 + __logf(ssum) + eb[t*NTAG + tid];
        }
        __syncthreads();
        if (tid < NTAG) al[tid] = na;
        __syncthreads();
    }

    if (tid == 0){
        float m = -1e30f;
        for (int j = 0; j < NTAG; j++) m = fmaxf(m, al[j] + endv[j]);
        float s = 0.f;
        for (int j = 0; j < NTAG; j++) s += __expf(al[j] + endv[j] - m);
        v[b] = num_s - (m + __logf(s));
    }
}

__global__ void final_reduce(const float* __restrict__ v, float* __restrict__ out){
    __shared__ float s[64];
    s[threadIdx.x] = v[threadIdx.x];
    __syncthreads();
    if (threadIdx.x == 0){
        float a = 0.f;
        for (int i = 0; i < 64; i++) a += s[i];
        out[0] = -(a / 64.f);
    }
}

// ------------------- launch -------------------
extern "C" void kernel_launch(void* const* d_in, const int* in_sizes, int n_in,
                              void* d_out, int out_size)
{
    const float* inputs = (const float*)d_in[0];
    const int*   tags   = (const int*)d_in[1];
    const float *Wih0f=(const float*)d_in[2],  *Whh0f=(const float*)d_in[3],
                *bih0f=(const float*)d_in[4],  *bhh0f=(const float*)d_in[5];
    const float *Wih0b=(const float*)d_in[6],  *Whh0b=(const float*)d_in[7],
                *bih0b=(const float*)d_in[8],  *bhh0b=(const float*)d_in[9];
    const float *Wih1f=(const float*)d_in[10], *Whh1f=(const float*)d_in[11],
                *bih1f=(const float*)d_in[12], *bhh1f=(const float*)d_in[13];
    const float *Wih1b=(const float*)d_in[14], *Whh1b=(const float*)d_in[15],
                *bih1b=(const float*)d_in[16], *bhh1b=(const float*)d_in[17];
    const float *gamma=(const float*)d_in[18], *beta=(const float*)d_in[19],
                *mean=(const float*)d_in[20],  *var=(const float*)d_in[21];
    const float *fc1w=(const float*)d_in[22], *fc1b=(const float*)d_in[23];
    const float *fc2w=(const float*)d_in[24], *fc2b=(const float*)d_in[25];
    const float *fc3w=(const float*)d_in[26], *fc3b=(const float*)d_in[27];
    const float *crfS=(const float*)d_in[28], *crfE=(const float*)d_in[29],
                *crfT=(const float*)d_in[30];

    bf16 *pInb,*pW0m,*pW1m,*pWh0f,*pWh0b,*pWh1f,*pWh1b;
    bf16 *pFc1w,*pFc2w,*pFc3w,*pX1,*pX2,*pF1,*pF2,*pPre;
    float *pB0m,*pB1m,*pFc1b,*pEm,*pV;
    cudaGetSymbolAddress((void**)&pInb, d_inb);
    cudaGetSymbolAddress((void**)&pW0m, d_W0m);
    cudaGetSymbolAddress((void**)&pW1m, d_W1m);
    cudaGetSymbolAddress((void**)&pWh0f, d_Wh0f);
    cudaGetSymbolAddress((void**)&pWh0b, d_Wh0b);
    cudaGetSymbolAddress((void**)&pWh1f, d_Wh1f);
    cudaGetSymbolAddress((void**)&pWh1b, d_Wh1b);
    cudaGetSymbolAddress((void**)&pB0m, d_b0m);
    cudaGetSymbolAddress((void**)&pB1m, d_b1m);
    cudaGetSymbolAddress((void**)&pFc1w, d_fc1wP);
    cudaGetSymbolAddress((void**)&pFc1b, d_fc1bP);
    cudaGetSymbolAddress((void**)&pFc2w, d_fc2wB);
    cudaGetSymbolAddress((void**)&pFc3w, d_fc3wB);
    cudaGetSymbolAddress((void**)&pPre, d_pre);
    cudaGetSymbolAddress((void**)&pX1, d_x1);
    cudaGetSymbolAddress((void**)&pX2, d_x2);
    cudaGetSymbolAddress((void**)&pF1, d_f1);
    cudaGetSymbolAddress((void**)&pF2, d_f2);
    cudaGetSymbolAddress((void**)&pEm, d_em);
    cudaGetSymbolAddress((void**)&pV, d_v);

    const int gemm_smem = 2*2*128*BRS*2;
    const int lstm_smem = (32*WSB + 64*WSB + 2*64*PSB)*2;
    cudaFuncSetAttribute(gemm_bf16, cudaFuncAttributeMaxDynamicSharedMemorySize, gemm_smem);
    cudaFuncSetAttribute(lstm_layer, cudaFuncAttributeMaxDynamicSharedMemorySize, lstm_smem);

    prep_all<<<2048,256>>>(inputs, Wih0f, Wih0b, Whh0f, Whh0b, Wih1f, Wih1b, Whh1f, Whh1b,
                           bih0f, bhh0f, bih0b, bhh0b, bih1f, bhh1f, bih1b, bhh1b,
                           fc2w, fc3w);
    prep_fc<<<512,256>>>(fc1w, fc1b, gamma, beta, mean, var);
    gemm_bf16<<<dim3(32,128),256,gemm_smem>>>(pInb, pW0m, pB0m, pPre, MROWS, 4096, 256, 0, 1);
    lstm_layer<<<128,256,lstm_smem>>>(pPre, pWh0f, pWh0b, pX1, 0);
    gemm_bf16<<<dim3(32,128),256,gemm_smem>>>(pX1, pW1m, pB1m, pPre, MROWS, 4096, 1024, 0, 1);
    lstm_layer<<<128,256,lstm_smem>>>(pPre, pWh1f, pWh1b, pX2, 256);
    gemm_bf16<<<dim3(4,128),256,gemm_smem>>>(pX2, pFc1w, pFc1b, pF1, MROWS, 512, 1024, 1, 1);
    gemm_bf16<<<dim3(2,128),256,gemm_smem>>>(pF1, pFc2w, fc2b, pF2, MROWS, 256, 512, 1, 1);
    gemm_bf16<<<dim3(1,128),256,gemm_smem>>>(pF2, pFc3w, fc3b, pEm, MROWS, NTAG, 256, 0, 0);
    crf_kernel<<<64,64>>>(pEm, tags, crfS, crfE, crfT, pV);
    final_reduce<<<1,64>>>(pV, (float*)d_out);
}

// round 12
// speedup vs baseline: 1.3735x; 1.0550x over previous
#include <cuda_runtime.h>
#include <cuda_bf16.h>
#include <cstdint>

#define BATCH 64
#define SEQ   256
#define HID   512
#define NTAG  48
#define MROWS (BATCH*SEQ)     // 16384
#define G4    2048
#define H2    1024

typedef __nv_bfloat16 bf16;
typedef __nv_bfloat162 bf162;

// ------------------- static device scratch -------------------
__device__ bf16  d_inb[16384*256];
__device__ bf16  d_W0m[4096*256];
__device__ bf16  d_W1m[4096*1024];
__device__ bf16  d_Wh0f[2048*512];
__device__ bf16  d_Wh0b[2048*512];
__device__ bf16  d_Wh1f[2048*512];
__device__ bf16  d_Wh1b[2048*512];
__device__ float d_b0m[4096];
__device__ float d_b1m[4096];
__device__ bf16  d_fc1wP[512*1024];
__device__ float d_fc1bP[512];
__device__ bf16  d_fc2wB[256*512];
__device__ bf16  d_fc3wB[48*256];
__device__ bf16  d_pre[(size_t)16384*4096];
__device__ bf16  d_x1[16384*1024];
__device__ bf16  d_x2[16384*1024];
__device__ bf16  d_f1[16384*512];
__device__ bf16  d_f2[16384*256];
__device__ float d_em[16384*48];
__device__ bf16  d_hbuf[2*2*BATCH*HID];   // [parity][dir][b][j]
__device__ float d_v[64];
__device__ int   d_slot[2][512];          // slot ns at index ns*8 (32B stride)

// ------------------- helpers -------------------
__device__ __forceinline__ void mma16r(float* c,
    unsigned a0, unsigned a1, unsigned a2, unsigned a3, unsigned b0, unsigned b1){
    asm volatile(
        "mma.sync.aligned.m16n8k16.row.col.f32.bf16.bf16.f32 "
        "{%0,%1,%2,%3}, {%4,%5,%6,%7}, {%8,%9}, {%0,%1,%2,%3};\n"
        : "+f"(c[0]), "+f"(c[1]), "+f"(c[2]), "+f"(c[3])
        : "r"(a0), "r"(a1), "r"(a2), "r"(a3), "r"(b0), "r"(b1));
}

__device__ __forceinline__ void ldsm4(unsigned& r0, unsigned& r1, unsigned& r2, unsigned& r3,
                                      unsigned addr){
    asm volatile("ldmatrix.sync.aligned.m8n8.x4.shared.b16 {%0,%1,%2,%3}, [%4];"
        : "=r"(r0), "=r"(r1), "=r"(r2), "=r"(r3) : "r"(addr));
}

__device__ __forceinline__ float fsig(float x){
    float t;
    asm("mul.f32 %0, %1, 0fBFB8AA3B;" : "=f"(t) : "f"(x));
    asm("ex2.approx.f32 %0, %0;" : "+f"(t));
    asm("add.f32 %0, %0, 0f3F800000;" : "+f"(t));
    asm("rcp.approx.f32 %0, %0;" : "+f"(t));
    return t;
}
__device__ __forceinline__ float ftanh(float x){
    float r; asm("tanh.approx.f32 %0, %1;" : "=f"(r) : "f"(x)); return r;
}

__device__ __forceinline__ void st_release(int* addr, int v){
    asm volatile("st.release.gpu.global.s32 [%0], %1;" :: "l"(addr), "r"(v) : "memory");
}
__device__ __forceinline__ int ld_acquire(const int* addr){
    int v;
    asm volatile("ld.acquire.gpu.global.s32 %0, [%1];" : "=r"(v) : "l"(addr) : "memory");
    return v;
}

__device__ __forceinline__ void cp16(void* smem, const void* gmem){
    unsigned sa = (unsigned)__cvta_generic_to_shared(smem);
    asm volatile("cp.async.cg.shared.global [%0], [%1], 16;" :: "r"(sa), "l"(gmem));
}
__device__ __forceinline__ void cp16z(void* smem, const void* gmem, int pred){
    unsigned sa = (unsigned)__cvta_generic_to_shared(smem);
    int bytes = pred ? 16 : 0;
    asm volatile("cp.async.cg.shared.global [%0], [%1], 16, %2;" :: "r"(sa), "l"(gmem), "r"(bytes));
}
__device__ __forceinline__ void cp_commit(){ asm volatile("cp.async.commit_group;"); }
__device__ __forceinline__ void cp_wait0(){ asm volatile("cp.async.wait_group 0;"); }
__device__ __forceinline__ void cp_wait1(){ asm volatile("cp.async.wait_group 1;"); }
__device__ __forceinline__ void cp_wait2(){ asm volatile("cp.async.wait_group 2;"); }

// ------------------- prep -------------------
// gate permutation: permuted col p -> unit j = (p>>5)*8 + ((p>>4)&1)*4 + ((p>>1)&3),
// gate g = ((p>>3)&1)*2 + (p&1); source row = g*512 + j
__device__ __forceinline__ int perm_src(int np2){
    int j  = ((np2 >> 5) << 3) + (((np2 >> 4) & 1) << 2) + ((np2 >> 1) & 3);
    int gt = (((np2 >> 3) & 1) << 1) + (np2 & 1);
    return gt*512 + j;
}

__global__ void prep_all(
    const float* __restrict__ inputs,
    const float* __restrict__ Wih0f, const float* __restrict__ Wih0b,
    const float* __restrict__ Whh0f, const float* __restrict__ Whh0b,
    const float* __restrict__ Wih1f, const float* __restrict__ Wih1b,
    const float* __restrict__ Whh1f, const float* __restrict__ Whh1b,
    const float* __restrict__ bih0f, const float* __restrict__ bhh0f,
    const float* __restrict__ bih0b, const float* __restrict__ bhh0b,
    const float* __restrict__ bih1f, const float* __restrict__ bhh1f,
    const float* __restrict__ bih1b, const float* __restrict__ bhh1b,
    const float* __restrict__ fc2w, const float* __restrict__ fc3w)
{
    const int NIN = 16384*256;
    const int NW0 = 4096*256;
    const int NW1 = 4096*1024;
    const int NWH = 2048*512;
    const int e0 = NIN;
    const int e1 = e0 + NW0;
    const int e2 = e1 + NW1;
    const int e3 = e2 + 4*NWH;
    const int e4 = e3 + 4096;
    const int e5 = e4 + 4096;
    const int e6 = e5 + 256*512;
    const int e7 = e6 + 48*256;
    const int total = e7 + 1024;
    int stride = gridDim.x * blockDim.x;
    for (int i = blockIdx.x*blockDim.x + threadIdx.x; i < total; i += stride){
        if (i < e0){
            d_inb[i] = __float2bfloat16_rn(inputs[i]);
        } else if (i < e1){
            int j = i - e0;
            int np = j >> 8, k = j & 255;
            int sr = perm_src(np & 2047);
            const float* src = (np < 2048) ? Wih0f : Wih0b;
            d_W0m[j] = __float2bfloat16_rn(src[sr*256 + k]);
        } else if (i < e2){
            int j = i - e1;
            int np = j >> 10, k = j & 1023;
            int sr = perm_src(np & 2047);
            const float* src = (np < 2048) ? Wih1f : Wih1b;
            d_W1m[j] = __float2bfloat16_rn(src[sr*1024 + k]);
        } else if (i < e3){
            int j = i - e2;
            int arr = j / NWH;
            int jj = j - arr*NWH;
            int np = jj >> 9, k = jj & 511;
            int sr = perm_src(np);
            const float* src = (arr==0)?Whh0f:(arr==1)?Whh0b:(arr==2)?Whh1f:Whh1b;
            bf16* dst = (arr==0)?d_Wh0f:(arr==1)?d_Wh0b:(arr==2)?d_Wh1f:d_Wh1b;
            dst[jj] = __float2bfloat16_rn(src[sr*512 + k]);
        } else if (i < e4){
            int np = i - e3;
            int sr = perm_src(np & 2047);
            d_b0m[np] = (np < 2048) ? (bih0f[sr] + bhh0f[sr]) : (bih0b[sr] + bhh0b[sr]);
        } else if (i < e5){
            int np = i - e4;
            int sr = perm_src(np & 2047);
            d_b1m[np] = (np < 2048) ? (bih1f[sr] + bhh1f[sr]) : (bih1b[sr] + bhh1b[sr]);
        } else if (i < e6){
            int j = i - e5;
            d_fc2wB[j] = __float2bfloat16_rn(fc2w[j]);
        } else if (i < e7){
            int j = i - e6;
            d_fc3wB[j] = __float2bfloat16_rn(fc3w[j]);
        } else {
            ((int*)d_slot)[i - e7] = 0;
        }
    }
}

// fold BN into fc1
__global__ void prep_fc(const float* __restrict__ fc1w, const float* __restrict__ fc1b,
                        const float* __restrict__ gamma, const float* __restrict__ beta,
                        const float* __restrict__ mean, const float* __restrict__ var)
{
    __shared__ float red[256];
    int r = blockIdx.x;
    int tid = threadIdx.x;
    float part = 0.f;
    for (int c = tid; c < 1024; c += 256){
        float sc = gamma[c] * rsqrtf(var[c] + 1e-5f);
        float tc = beta[c] - mean[c]*sc;
        float w = fc1w[r*1024 + c];
        d_fc1wP[r*1024 + c] = __float2bfloat16_rn(w * sc);
        part += w * tc;
    }
    red[tid] = part;
    __syncthreads();
    for (int off = 128; off > 0; off >>= 1){
        if (tid < off) red[tid] += red[tid + off];
        __syncthreads();
    }
    if (tid == 0) d_fc1bP[r] = fc1b[r] + red[0];
}

// ------------------- bf16 GEMM: C = A(MxK) @ W(NxK)^T + bias -------------------
#define BRS 40
__global__ __launch_bounds__(256) void gemm_bf16(
    const bf16* __restrict__ A, const bf16* __restrict__ W,
    const float* __restrict__ bias, void* __restrict__ Cv,
    int M, int N, int K, int relu, int outBf)
{
    extern __shared__ bf16 smb[];
    bf16* As = smb;
    bf16* Bs = smb + 2*128*BRS;
    int tid  = threadIdx.x;
    int warp = tid >> 5, lane = tid & 31;
    int wm = warp >> 2, wn = warp & 3;
    int g = lane >> 2, tg = lane & 3;
    int m0 = blockIdx.y*128, n0 = blockIdx.x*128;

    float acc[4][4][4];
#pragma unroll
    for (int a = 0; a < 4; a++)
#pragma unroll
        for (int b = 0; b < 4; b++)
#pragma unroll
            for (int c = 0; c < 4; c++) acc[a][b][c] = 0.f;

    int KT = K >> 5;

    auto stage = [&](int kt, int bb){
        const bf16* Ag = A + (size_t)m0*K + kt*32;
#pragma unroll
        for (int i = 0; i < 2; i++){
            int q = i*256 + tid;
            int r = q >> 2;
            int c = (q & 3) * 8;
            cp16(&As[bb*128*BRS + r*BRS + c], Ag + (size_t)r*K + c);
        }
        const bf16* Wg = W + kt*32;
#pragma unroll
        for (int i = 0; i < 2; i++){
            int q = i*256 + tid;
            int r = q >> 2;
            int c = (q & 3) * 8;
            int nr = n0 + r;
            int nc = nr < N ? nr : 0;
            cp16z(&Bs[bb*128*BRS + r*BRS + c], Wg + (size_t)nc*K + c, nr < N);
        }
        cp_commit();
    };

    stage(0, 0);
    if (KT > 1) stage(1, 1);

    for (int kt = 0; kt < KT; kt++){
        if (kt < KT-1) cp_wait1(); else cp_wait0();
        __syncthreads();
        int bb = kt & 1;
        const bf16* Ab = As + bb*128*BRS + (wm*64)*BRS;
        const bf16* Bb = Bs + bb*128*BRS + (wn*32)*BRS;
#pragma unroll
        for (int kk = 0; kk < 2; kk++){
            int kc = kk*16 + tg*2;
            unsigned af[4][4], bf[4][2];
#pragma unroll
            for (int mt = 0; mt < 4; mt++){
                const bf16* p = Ab + (mt*16 + g)*BRS + kc;
                af[mt][0] = *(const unsigned*)p;
                af[mt][1] = *(const unsigned*)(p + 8*BRS);
                af[mt][2] = *(const unsigned*)(p + 8);
                af[mt][3] = *(const unsigned*)(p + 8*BRS + 8);
            }
#pragma unroll
            for (int nt = 0; nt < 4; nt++){
                const bf16* p = Bb + (nt*8 + g)*BRS + kc;
                bf[nt][0] = *(const unsigned*)p;
                bf[nt][1] = *(const unsigned*)(p + 8);
            }
#pragma unroll
            for (int mt = 0; mt < 4; mt++)
#pragma unroll
                for (int nt = 0; nt < 4; nt++)
                    mma16r(acc[mt][nt], af[mt][0], af[mt][1], af[mt][2], af[mt][3],
                           bf[nt][0], bf[nt][1]);
        }
        __syncthreads();
        if (kt + 2 < KT) stage(kt+2, bb);
    }

#pragma unroll
    for (int mt = 0; mt < 4; mt++){
        int row = m0 + wm*64 + mt*16 + g;
#pragma unroll
        for (int nt = 0; nt < 4; nt++){
            int col = n0 + wn*32 + nt*8 + 2*tg;
            if (col < N){
                float b0 = bias[col], b1 = bias[col+1];
                float v0 = acc[mt][nt][0] + b0;
                float v1 = acc[mt][nt][1] + b1;
                float v2 = acc[mt][nt][2] + b0;
                float v3 = acc[mt][nt][3] + b1;
                if (relu){
                    v0 = fmaxf(v0, 0.f); v1 = fmaxf(v1, 0.f);
                    v2 = fmaxf(v2, 0.f); v3 = fmaxf(v3, 0.f);
                }
                if (outBf){
                    bf16* C16 = (bf16*)Cv;
                    *(bf162*)&C16[(size_t)row*N + col]     = __floats2bfloat162_rn(v0, v1);
                    *(bf162*)&C16[(size_t)(row+8)*N + col] = __floats2bfloat162_rn(v2, v3);
                } else {
                    float* C = (float*)Cv;
                    *(float2*)&C[(size_t)row*N + col]     = make_float2(v0, v1);
                    *(float2*)&C[(size_t)(row+8)*N + col] = make_float2(v2, v3);
                }
            }
        }
    }
}

// ------------------- persistent bidirectional LSTM layer -------------------
// 128 blocks x 256 threads. dir = bx>>6, ns = bx&63. Block owns permuted gate cols
// [ns*32,+32) = units [ns*8,+8). 8 warps: wm=warp>>1, wn=warp&1.
// Thread (g,tg) holds full i/f/g/o of unit wn*4+tg for rows wm*16+g and +8.
// Whh fragments register-resident (loaded once); gates/cell state in registers;
// h/out stores shuffle-packed to 8B per g-group (lane tg==0 stores).
#define WSB 520
#define PSB 40
__global__ __launch_bounds__(256) void lstm_layer(
    const bf16* __restrict__ pre,
    const bf16* __restrict__ whhF, const bf16* __restrict__ whhB,
    bf16* __restrict__ out, int gen0)
{
    extern __shared__ char smraw[];
    bf16* whh_s = (bf16*)smraw;                  // [32][WSB] (staging only)
    bf16* h_s   = whh_s + 32*WSB;                // [64][WSB]
    bf16* pre_s = h_s + 64*WSB;                  // [2][64][PSB]

    int tid = threadIdx.x;
    int warp = tid >> 5, lane = tid & 31;
    int wm = warp >> 1, wn = warp & 1;
    int g = lane >> 2, tg = lane & 3;
    int dir = blockIdx.x >> 6;
    int ns  = blockIdx.x & 63;
    int n0  = ns*32;
    int j0  = ns*8;
    const bf16* whh = dir ? whhB : whhF;
    int* slots = &d_slot[dir][0];

    // stage Whh slice to smem (once), then lift fragments to registers
#pragma unroll
    for (int i = 0; i < 8; i++){
        int q = i*256 + tid;
        int r = q >> 6;
        int c = (q & 63) * 8;
        cp16(&whh_s[r*WSB + c], &whh[(n0 + r)*512 + c]);
    }
    cp_commit();

    // ldmatrix lane addresses
    int lrow = lane & 15;
    int lcol = (lane >> 4) * 16;
    unsigned hbase = (unsigned)__cvta_generic_to_shared(h_s);
    unsigned wbase = (unsigned)__cvta_generic_to_shared(whh_s);
    unsigned aAddr = hbase + (unsigned)((wm*16 + lrow)*WSB)*2u + lcol;
    unsigned bAddr = wbase + (unsigned)((wn*16 + lrow)*WSB)*2u + lcol;

    // gate-phase coords
    int rrA = wm*16 + g;
    int rrB = rrA + 8;
    int pcI = wn*16 + 2*tg;       // i,f pair col within pre_s row
    int ju  = j0 + wn*4;          // packed-store unit base

    // pre staging coords
    int pr_ = tid >> 2, pc_ = (tid & 3)*8;

    float cA = 0.f, cB = 0.f;

    cp_wait0();
    __syncthreads();

    // register-resident Whh fragments: 32 k16 iters x 4 regs
    unsigned br[32][4];
#pragma unroll
    for (int k16 = 0; k16 < 32; k16++)
        ldsm4(br[k16][0], br[k16][1], br[k16][2], br[k16][3], bAddr + (unsigned)k16*32u);

    // prefetch pre for step 0
    {
        int t0 = dir ? (SEQ-1) : 0;
        cp16(&pre_s[pr_*PSB + pc_], &pre[((size_t)(pr_*SEQ + t0))*4096 + dir*2048 + n0 + pc_]);
        cp_commit();
    }

    for (int s = 0; s < SEQ; s++){
        int t  = dir ? (SEQ-1 - s) : s;
        int rp = s & 1;
        int wp = rp ^ 1;

        // coalesced h staging: 2 chunks (k [0,256) and [256,512))
        if (s > 0){
            const bf16* hsrc = d_hbuf + (size_t)(rp*2 + dir)*BATCH*HID;
#pragma unroll
            for (int i = 0; i < 8; i++){
                int q = i*256 + tid;
                int r = q >> 5;
                int c = (q & 31) * 8;
                cp16(&h_s[r*WSB + c], &hsrc[r*HID + c]);
            }
            cp_commit();
#pragma unroll
            for (int i = 0; i < 8; i++){
                int q = i*256 + tid;
                int r = q >> 5;
                int c = (q & 31) * 8 + 256;
                cp16(&h_s[r*WSB + c], &hsrc[r*HID + c]);
            }
            cp_commit();
        }
        // prefetch pre for step s+1
        if (s + 1 < SEQ){
            int tn = dir ? (SEQ-2 - s) : (s + 1);
            bf16* pb = pre_s + ((s+1) & 1)*64*PSB;
            cp16(&pb[pr_*PSB + pc_], &pre[((size_t)(pr_*SEQ + tn))*4096 + dir*2048 + n0 + pc_]);
        }
        cp_commit();

        float acc[2][4];
#pragma unroll
        for (int b = 0; b < 2; b++)
#pragma unroll
            for (int c = 0; c < 4; c++) acc[b][c] = 0.f;

        if (s > 0){
            cp_wait2();             // h chunk0 ready (and pre(s))
            __syncthreads();
#pragma unroll
            for (int k16 = 0; k16 < 16; k16++){
                unsigned off = (unsigned)k16 * 32u;
                unsigned a0,a1,a2,a3;
                ldsm4(a0,a1,a2,a3, aAddr + off);
                mma16r(acc[0], a0,a1,a2,a3, br[k16][0], br[k16][2]);
                mma16r(acc[1], a0,a1,a2,a3, br[k16][1], br[k16][3]);
            }
            cp_wait1();             // h chunk1 ready
            __syncthreads();
#pragma unroll
            for (int k16 = 16; k16 < 32; k16++){
                unsigned off = (unsigned)k16 * 32u;
                unsigned a0,a1,a2,a3;
                ldsm4(a0,a1,a2,a3, aAddr + off);
                mma16r(acc[0], a0,a1,a2,a3, br[k16][0], br[k16][2]);
                mma16r(acc[1], a0,a1,a2,a3, br[k16][1], br[k16][3]);
            }
        } else {
            cp_wait1();             // pre(0) ready
            __syncthreads();
        }

        // in-register gate update: thread owns unit wn*4+tg, rows rrA/rrB
        unsigned pkA, pkB;
        {
            const bf16* pcur = pre_s + (s & 1)*64*PSB;
            bf162 pIFA = *(const bf162*)&pcur[rrA*PSB + pcI];
            bf162 pGOA = *(const bf162*)&pcur[rrA*PSB + pcI + 8];
            bf162 pIFB = *(const bf162*)&pcur[rrB*PSB + pcI];
            bf162 pGOB = *(const bf162*)&pcur[rrB*PSB + pcI + 8];

            float iA = acc[0][0] + __low2float(pIFA);
            float fA = acc[0][1] + __high2float(pIFA);
            float gA = acc[1][0] + __low2float(pGOA);
            float oA = acc[1][1] + __high2float(pGOA);
            cA = fsig(fA)*cA + fsig(iA)*ftanh(gA);
            float hA = fsig(oA)*ftanh(cA);

            float iB = acc[0][2] + __low2float(pIFB);
            float fB = acc[0][3] + __high2float(pIFB);
            float gB = acc[1][2] + __low2float(pGOB);
            float oB = acc[1][3] + __high2float(pGOB);
            cB = fsig(fB)*cB + fsig(iB)*ftanh(gB);
            float hB = fsig(oB)*ftanh(cB);

            bf16 hAb = __float2bfloat16_rn(hA);
            bf16 hBb = __float2bfloat16_rn(hB);
            unsigned vA = (unsigned)*(unsigned short*)&hAb;
            unsigned vB = (unsigned)*(unsigned short*)&hBb;

            // pack 4 units (tg=0..3) into lane tg==0: {u0|u1<<16, u2|u3<<16}
            unsigned loA = vA | (__shfl_xor_sync(0xffffffffu, vA, 1) << 16);
            unsigned hiA = __shfl_xor_sync(0xffffffffu, loA, 2);
            unsigned loB = vB | (__shfl_xor_sync(0xffffffffu, vB, 1) << 16);
            unsigned hiB = __shfl_xor_sync(0xffffffffu, loB, 2);
            pkA = loA; pkB = loB;   // keep for out stores (tg==0 lanes use these)

            if (tg == 0){
                bf16* hdst = d_hbuf + (size_t)(wp*2 + dir)*BATCH*HID;
                *(uint2*)&hdst[rrA*HID + ju] = make_uint2(loA, hiA);
                *(uint2*)&hdst[rrB*HID + ju] = make_uint2(loB, hiB);
                pkA = hiA; pkB = hiB;   // stash hi halves in pkA/pkB? no — need both
            }
            // re-gather hi for out stores after release (recompute cheaply below)
            pkA = loA; pkB = loB;
            if (tg == 0){ pkA = loA; pkB = loB; }
            // store hi parts via registers captured above
            // (out stores done after release below using loA/hiA/loB/hiB)
            // To keep them alive:
            pkA = loA; pkB = hiA;
            // stash B's pair in shared-free registers:
            // (use vA/vB as carriers)
            vA = loB; vB = hiB;

            // one-hop barrier: release -> out stores overlap -> 2-warp poll
            __syncthreads();
            int target = gen0 + s + 1;
            if (tid == 0) st_release(&slots[ns*8], target);
            if (tg == 0){
                *(uint2*)&out[(size_t)(rrA*SEQ + t)*H2 + dir*HID + ju] = make_uint2(pkA, pkB);
                *(uint2*)&out[(size_t)(rrB*SEQ + t)*H2 + dir*HID + ju] = make_uint2(vA, vB);
            }
            if (tid < 64){
                while (ld_acquire(&slots[tid*8]) < target) { }
            }
            __syncthreads();
        }
    }
}

// ------------------- CRF: alpha' = m + log(exp(alpha-m) @ exp(T)) + em -------------------
__global__ void crf_kernel(const float* __restrict__ em, const int* __restrict__ tags,
                           const float* __restrict__ start, const float* __restrict__ endv,
                           const float* __restrict__ trans, float* __restrict__ v)
{
    __shared__ float E[NTAG*49];
    __shared__ float al[NTAG];
    __shared__ float p[NTAG];
    __shared__ float red[64];
    __shared__ float num_s;
    int b = blockIdx.x;
    int tid = threadIdx.x;
    const int* tg = tags + b*SEQ;
    const float* eb = em + b*SEQ*NTAG;

    for (int q = tid; q < NTAG*NTAG; q += 64){
        int i = q / NTAG, j = q - i*NTAG;
        E[i*49 + j] = __expf(trans[q]);
    }
    float part = 0.f;
    for (int t = tid; t < SEQ; t += 64){
        int tt = tg[t];
        part += eb[t*NTAG + tt];
        if (t < SEQ-1) part += trans[tt*NTAG + tg[t+1]];
    }
    red[tid] = part;
    if (tid < NTAG) al[tid] = start[tid] + eb[tid];
    __syncthreads();
    if (tid == 0){
        float s = 0.f;
        for (int i = 0; i < 64; i++) s += red[i];
        num_s = s + start[tg[0]] + endv[tg[SEQ-1]];
    }
    __syncthreads();

    for (int t = 1; t < SEQ; t++){
        if (tid < NTAG) p[tid] = __expf(al[tid] - al[0]);
        __syncthreads();
        float na = 0.f;
        if (tid < NTAG){
            float m0 = al[0];
            float ssum = 0.f;
#pragma unroll 8
            for (int i = 0; i < NTAG; i++) ssum += p[i] * E[i*49 + tid];
            na = m0 + __logf(ssum) + eb[t*NTAG + tid];
        }
        __syncthreads();
        if (tid < NTAG) al[tid] = na;
        __syncthreads();
    }

    if (tid == 0){
        float m = -1e30f;
        for (int j = 0; j < NTAG; j++) m = fmaxf(m, al[j] + endv[j]);
        float s = 0.f;
        for (int j = 0; j < NTAG; j++) s += __expf(al[j] + endv[j] - m);
        v[b] = num_s - (m + __logf(s));
    }
}

__global__ void final_reduce(const float* __restrict__ v, float* __restrict__ out){
    __shared__ float s[64];
    s[threadIdx.x] = v[threadIdx.x];
    __syncthreads();
    if (threadIdx.x == 0){
        float a = 0.f;
        for (int i = 0; i < 64; i++) a += s[i];
        out[0] = -(a / 64.f);
    }
}

// ------------------- launch -------------------
extern "C" void kernel_launch(void* const* d_in, const int* in_sizes, int n_in,
                              void* d_out, int out_size)
{
    const float* inputs = (const float*)d_in[0];
    const int*   tags   = (const int*)d_in[1];
    const float *Wih0f=(const float*)d_in[2],  *Whh0f=(const float*)d_in[3],
                *bih0f=(const float*)d_in[4],  *bhh0f=(const float*)d_in[5];
    const float *Wih0b=(const float*)d_in[6],  *Whh0b=(const float*)d_in[7],
                *bih0b=(const float*)d_in[8],  *bhh0b=(const float*)d_in[9];
    const float *Wih1f=(const float*)d_in[10], *Whh1f=(const float*)d_in[11],
                *bih1f=(const float*)d_in[12], *bhh1f=(const float*)d_in[13];
    const float *Wih1b=(const float*)d_in[14], *Whh1b=(const float*)d_in[15],
                *bih1b=(const float*)d_in[16], *bhh1b=(const float*)d_in[17];
    const float *gamma=(const float*)d_in[18], *beta=(const float*)d_in[19],
                *mean=(const float*)d_in[20],  *var=(const float*)d_in[21];
    const float *fc1w=(const float*)d_in[22], *fc1b=(const float*)d_in[23];
    const float *fc2w=(const float*)d_in[24], *fc2b=(const float*)d_in[25];
    const float *fc3w=(const float*)d_in[26], *fc3b=(const float*)d_in[27];
    const float *crfS=(const float*)d_in[28], *crfE=(const float*)d_in[29],
                *crfT=(const float*)d_in[30];

    bf16 *pInb,*pW0m,*pW1m,*pWh0f,*pWh0b,*pWh1f,*pWh1b;
    bf16 *pFc1w,*pFc2w,*pFc3w,*pX1,*pX2,*pF1,*pF2,*pPre;
    float *pB0m,*pB1m,*pFc1b,*pEm,*pV;
    cudaGetSymbolAddress((void**)&pInb, d_inb);
    cudaGetSymbolAddress((void**)&pW0m, d_W0m);
    cudaGetSymbolAddress((void**)&pW1m, d_W1m);
    cudaGetSymbolAddress((void**)&pWh0f, d_Wh0f);
    cudaGetSymbolAddress((void**)&pWh0b, d_Wh0b);
    cudaGetSymbolAddress((void**)&pWh1f, d_Wh1f);
    cudaGetSymbolAddress((void**)&pWh1b, d_Wh1b);
    cudaGetSymbolAddress((void**)&pB0m, d_b0m);
    cudaGetSymbolAddress((void**)&pB1m, d_b1m);
    cudaGetSymbolAddress((void**)&pFc1w, d_fc1wP);
    cudaGetSymbolAddress((void**)&pFc1b, d_fc1bP);
    cudaGetSymbolAddress((void**)&pFc2w, d_fc2wB);
    cudaGetSymbolAddress((void**)&pFc3w, d_fc3wB);
    cudaGetSymbolAddress((void**)&pPre, d_pre);
    cudaGetSymbolAddress((void**)&pX1, d_x1);
    cudaGetSymbolAddress((void**)&pX2, d_x2);
    cudaGetSymbolAddress((void**)&pF1, d_f1);
    cudaGetSymbolAddress((void**)&pF2, d_f2);
    cudaGetSymbolAddress((void**)&pEm, d_em);
    cudaGetSymbolAddress((void**)&pV, d_v);

    const int gemm_smem = 2*2*128*BRS*2;
    const int lstm_smem = (32*WSB + 64*WSB + 2*64*PSB)*2;
    cudaFuncSetAttribute(gemm_bf16, cudaFuncAttributeMaxDynamicSharedMemorySize, gemm_smem);
    cudaFuncSetAttribute(lstm_layer, cudaFuncAttributeMaxDynamicSharedMemorySize, lstm_smem);

    prep_all<<<2048,256>>>(inputs, Wih0f, Wih0b, Whh0f, Whh0b, Wih1f, Wih1b, Whh1f, Whh1b,
                           bih0f, bhh0f, bih0b, bhh0b, bih1f, bhh1f, bih1b, bhh1b,
                           fc2w, fc3w);
    prep_fc<<<512,256>>>(fc1w, fc1b, gamma, beta, mean, var);
    gemm_bf16<<<dim3(32,128),256,gemm_smem>>>(pInb, pW0m, pB0m, pPre, MROWS, 4096, 256, 0, 1);
    lstm_layer<<<128,256,lstm_smem>>>(pPre, pWh0f, pWh0b, pX1, 0);
    gemm_bf16<<<dim3(32,128),256,gemm_smem>>>(pX1, pW1m, pB1m, pPre, MROWS, 4096, 1024, 0, 1);
    lstm_layer<<<128,256,lstm_smem>>>(pPre, pWh1f, pWh1b, pX2, 256);
    gemm_bf16<<<dim3(4,128),256,gemm_smem>>>(pX2, pFc1w, pFc1b, pF1, MROWS, 512, 1024, 1, 1);
    gemm_bf16<<<dim3(2,128),256,gemm_smem>>>(pF1, pFc2w, fc2b, pF2, MROWS, 256, 512, 1, 1);
    gemm_bf16<<<dim3(1,128),256,gemm_smem>>>(pF2, pFc3w, fc3b, pEm, MROWS, NTAG, 256, 0, 0);
    crf_kernel<<<64,64>>>(pEm, tags, crfS, crfE, crfT, pV);
    final_reduce<<<1,64>>>(pV, (float*)d_out);
}

// round 13
// speedup vs baseline: 1.6314x; 1.1877x over previous
#include <cuda_runtime.h>
#include <cuda_bf16.h>
#include <cstdint>

#define BATCH 64
#define SEQ   256
#define HID   512
#define NTAG  48
#define MROWS (BATCH*SEQ)     // 16384
#define G4    2048
#define H2    1024

typedef __nv_bfloat16 bf16;
typedef __nv_bfloat162 bf162;

// ------------------- static device scratch -------------------
__device__ bf16  d_inb[16384*256];
__device__ bf16  d_W0m[4096*256];
__device__ bf16  d_W1m[4096*1024];
__device__ bf16  d_Wh0f[2048*512];
__device__ bf16  d_Wh0b[2048*512];
__device__ bf16  d_Wh1f[2048*512];
__device__ bf16  d_Wh1b[2048*512];
__device__ float d_b0m[4096];
__device__ float d_b1m[4096];
__device__ bf16  d_fc1wP[512*1024];
__device__ float d_fc1bP[512];
__device__ bf16  d_fc2wB[256*512];
__device__ bf16  d_fc3wB[48*256];
__device__ bf16  d_pre[(size_t)16384*4096];
__device__ bf16  d_x1[16384*1024];
__device__ bf16  d_x2[16384*1024];
__device__ bf16  d_f1[16384*512];
__device__ bf16  d_f2[16384*256];
__device__ float d_em[16384*48];
__device__ bf16  d_hbuf[2*2*BATCH*HID];   // [parity][dir][b][j]
__device__ float d_v[64];
__device__ int   d_slot[2][2048];         // slot ns at index ns*32 (128B stride)

// ------------------- helpers -------------------
__device__ __forceinline__ void mma16r(float* c,
    unsigned a0, unsigned a1, unsigned a2, unsigned a3, unsigned b0, unsigned b1){
    asm volatile(
        "mma.sync.aligned.m16n8k16.row.col.f32.bf16.bf16.f32 "
        "{%0,%1,%2,%3}, {%4,%5,%6,%7}, {%8,%9}, {%0,%1,%2,%3};\n"
        : "+f"(c[0]), "+f"(c[1]), "+f"(c[2]), "+f"(c[3])
        : "r"(a0), "r"(a1), "r"(a2), "r"(a3), "r"(b0), "r"(b1));
}

__device__ __forceinline__ void ldsm4(unsigned& r0, unsigned& r1, unsigned& r2, unsigned& r3,
                                      unsigned addr){
    asm volatile("ldmatrix.sync.aligned.m8n8.x4.shared.b16 {%0,%1,%2,%3}, [%4];"
        : "=r"(r0), "=r"(r1), "=r"(r2), "=r"(r3) : "r"(addr));
}

__device__ __forceinline__ float fsig(float x){
    float t;
    asm("mul.f32 %0, %1, 0fBFB8AA3B;" : "=f"(t) : "f"(x));
    asm("ex2.approx.f32 %0, %0;" : "+f"(t));
    asm("add.f32 %0, %0, 0f3F800000;" : "+f"(t));
    asm("rcp.approx.f32 %0, %0;" : "+f"(t));
    return t;
}
__device__ __forceinline__ float ftanh(float x){
    float r; asm("tanh.approx.f32 %0, %1;" : "=f"(r) : "f"(x)); return r;
}

__device__ __forceinline__ void st_release(int* addr, int v){
    asm volatile("st.release.gpu.global.s32 [%0], %1;" :: "l"(addr), "r"(v) : "memory");
}
__device__ __forceinline__ int ld_acquire(const int* addr){
    int v;
    asm volatile("ld.acquire.gpu.global.s32 %0, [%1];" : "=r"(v) : "l"(addr) : "memory");
    return v;
}

__device__ __forceinline__ void cp16(void* smem, const void* gmem){
    unsigned sa = (unsigned)__cvta_generic_to_shared(smem);
    asm volatile("cp.async.cg.shared.global [%0], [%1], 16;" :: "r"(sa), "l"(gmem));
}
__device__ __forceinline__ void cp16z(void* smem, const void* gmem, int pred){
    unsigned sa = (unsigned)__cvta_generic_to_shared(smem);
    int bytes = pred ? 16 : 0;
    asm volatile("cp.async.cg.shared.global [%0], [%1], 16, %2;" :: "r"(sa), "l"(gmem), "r"(bytes));
}
__device__ __forceinline__ void cp_commit(){ asm volatile("cp.async.commit_group;"); }
__device__ __forceinline__ void cp_wait0(){ asm volatile("cp.async.wait_group 0;"); }
__device__ __forceinline__ void cp_wait1(){ asm volatile("cp.async.wait_group 1;"); }
__device__ __forceinline__ void cp_wait2(){ asm volatile("cp.async.wait_group 2;"); }

// ------------------- prep -------------------
// gate permutation (R9): out row n' -> src row (n'&3)*512 + (n'>>2)
__global__ void prep_all(
    const float* __restrict__ inputs,
    const float* __restrict__ Wih0f, const float* __restrict__ Wih0b,
    const float* __restrict__ Whh0f, const float* __restrict__ Whh0b,
    const float* __restrict__ Wih1f, const float* __restrict__ Wih1b,
    const float* __restrict__ Whh1f, const float* __restrict__ Whh1b,
    const float* __restrict__ bih0f, const float* __restrict__ bhh0f,
    const float* __restrict__ bih0b, const float* __restrict__ bhh0b,
    const float* __restrict__ bih1f, const float* __restrict__ bhh1f,
    const float* __restrict__ bih1b, const float* __restrict__ bhh1b,
    const float* __restrict__ fc2w, const float* __restrict__ fc3w)
{
    const int NIN = 16384*256;
    const int NW0 = 4096*256;
    const int NW1 = 4096*1024;
    const int NWH = 2048*512;
    const int e0 = NIN;
    const int e1 = e0 + NW0;
    const int e2 = e1 + NW1;
    const int e3 = e2 + 4*NWH;
    const int e4 = e3 + 4096;
    const int e5 = e4 + 4096;
    const int e6 = e5 + 256*512;
    const int e7 = e6 + 48*256;
    const int total = e7 + 4096;        // ctrl: 4096 slot ints
    int stride = gridDim.x * blockDim.x;
    for (int i = blockIdx.x*blockDim.x + threadIdx.x; i < total; i += stride){
        if (i < e0){
            d_inb[i] = __float2bfloat16_rn(inputs[i]);
        } else if (i < e1){
            int j = i - e0;
            int np = j >> 8, k = j & 255;
            int np2 = np & 2047;
            int sr = (np2 & 3)*512 + (np2 >> 2);
            const float* src = (np < 2048) ? Wih0f : Wih0b;
            d_W0m[j] = __float2bfloat16_rn(src[sr*256 + k]);
        } else if (i < e2){
            int j = i - e1;
            int np = j >> 10, k = j & 1023;
            int np2 = np & 2047;
            int sr = (np2 & 3)*512 + (np2 >> 2);
            const float* src = (np < 2048) ? Wih1f : Wih1b;
            d_W1m[j] = __float2bfloat16_rn(src[sr*1024 + k]);
        } else if (i < e3){
            int j = i - e2;
            int arr = j / NWH;
            int jj = j - arr*NWH;
            int np = jj >> 9, k = jj & 511;
            int sr = (np & 3)*512 + (np >> 2);
            const float* src = (arr==0)?Whh0f:(arr==1)?Whh0b:(arr==2)?Whh1f:Whh1b;
            bf16* dst = (arr==0)?d_Wh0f:(arr==1)?d_Wh0b:(arr==2)?d_Wh1f:d_Wh1b;
            dst[jj] = __float2bfloat16_rn(src[sr*512 + k]);
        } else if (i < e4){
            int np = i - e3;
            int np2 = np & 2047;
            int sr = (np2 & 3)*512 + (np2 >> 2);
            d_b0m[np] = (np < 2048) ? (bih0f[sr] + bhh0f[sr]) : (bih0b[sr] + bhh0b[sr]);
        } else if (i < e5){
            int np = i - e4;
            int np2 = np & 2047;
            int sr = (np2 & 3)*512 + (np2 >> 2);
            d_b1m[np] = (np < 2048) ? (bih1f[sr] + bhh1f[sr]) : (bih1b[sr] + bhh1b[sr]);
        } else if (i < e6){
            int j = i - e5;
            d_fc2wB[j] = __float2bfloat16_rn(fc2w[j]);
        } else if (i < e7){
            int j = i - e6;
            d_fc3wB[j] = __float2bfloat16_rn(fc3w[j]);
        } else {
            ((int*)d_slot)[i - e7] = 0;
        }
    }
}

// fold BN into fc1
__global__ void prep_fc(const float* __restrict__ fc1w, const float* __restrict__ fc1b,
                        const float* __restrict__ gamma, const float* __restrict__ beta,
                        const float* __restrict__ mean, const float* __restrict__ var)
{
    __shared__ float red[256];
    int r = blockIdx.x;
    int tid = threadIdx.x;
    float part = 0.f;
    for (int c = tid; c < 1024; c += 256){
        float sc = gamma[c] * rsqrtf(var[c] + 1e-5f);
        float tc = beta[c] - mean[c]*sc;
        float w = fc1w[r*1024 + c];
        d_fc1wP[r*1024 + c] = __float2bfloat16_rn(w * sc);
        part += w * tc;
    }
    red[tid] = part;
    __syncthreads();
    for (int off = 128; off > 0; off >>= 1){
        if (tid < off) red[tid] += red[tid + off];
        __syncthreads();
    }
    if (tid == 0) d_fc1bP[r] = fc1b[r] + red[0];
}

// ------------------- bf16 GEMM: C = A(MxK) @ W(NxK)^T + bias -------------------
#define BRS 40
__global__ __launch_bounds__(256) void gemm_bf16(
    const bf16* __restrict__ A, const bf16* __restrict__ W,
    const float* __restrict__ bias, void* __restrict__ Cv,
    int M, int N, int K, int relu, int outBf)
{
    extern __shared__ bf16 smb[];
    bf16* As = smb;
    bf16* Bs = smb + 2*128*BRS;
    int tid  = threadIdx.x;
    int warp = tid >> 5, lane = tid & 31;
    int wm = warp >> 2, wn = warp & 3;
    int g = lane >> 2, tg = lane & 3;
    int m0 = blockIdx.y*128, n0 = blockIdx.x*128;

    float acc[4][4][4];
#pragma unroll
    for (int a = 0; a < 4; a++)
#pragma unroll
        for (int b = 0; b < 4; b++)
#pragma unroll
            for (int c = 0; c < 4; c++) acc[a][b][c] = 0.f;

    int KT = K >> 5;

    auto stage = [&](int kt, int bb){
        const bf16* Ag = A + (size_t)m0*K + kt*32;
#pragma unroll
        for (int i = 0; i < 2; i++){
            int q = i*256 + tid;
            int r = q >> 2;
            int c = (q & 3) * 8;
            cp16(&As[bb*128*BRS + r*BRS + c], Ag + (size_t)r*K + c);
        }
        const bf16* Wg = W + kt*32;
#pragma unroll
        for (int i = 0; i < 2; i++){
            int q = i*256 + tid;
            int r = q >> 2;
            int c = (q & 3) * 8;
            int nr = n0 + r;
            int nc = nr < N ? nr : 0;
            cp16z(&Bs[bb*128*BRS + r*BRS + c], Wg + (size_t)nc*K + c, nr < N);
        }
        cp_commit();
    };

    stage(0, 0);
    if (KT > 1) stage(1, 1);

    for (int kt = 0; kt < KT; kt++){
        if (kt < KT-1) cp_wait1(); else cp_wait0();
        __syncthreads();
        int bb = kt & 1;
        const bf16* Ab = As + bb*128*BRS + (wm*64)*BRS;
        const bf16* Bb = Bs + bb*128*BRS + (wn*32)*BRS;
#pragma unroll
        for (int kk = 0; kk < 2; kk++){
            int kc = kk*16 + tg*2;
            unsigned af[4][4], bf[4][2];
#pragma unroll
            for (int mt = 0; mt < 4; mt++){
                const bf16* p = Ab + (mt*16 + g)*BRS + kc;
                af[mt][0] = *(const unsigned*)p;
                af[mt][1] = *(const unsigned*)(p + 8*BRS);
                af[mt][2] = *(const unsigned*)(p + 8);
                af[mt][3] = *(const unsigned*)(p + 8*BRS + 8);
            }
#pragma unroll
            for (int nt = 0; nt < 4; nt++){
                const bf16* p = Bb + (nt*8 + g)*BRS + kc;
                bf[nt][0] = *(const unsigned*)p;
                bf[nt][1] = *(const unsigned*)(p + 8);
            }
#pragma unroll
            for (int mt = 0; mt < 4; mt++)
#pragma unroll
                for (int nt = 0; nt < 4; nt++)
                    mma16r(acc[mt][nt], af[mt][0], af[mt][1], af[mt][2], af[mt][3],
                           bf[nt][0], bf[nt][1]);
        }
        __syncthreads();
        if (kt + 2 < KT) stage(kt+2, bb);
    }

#pragma unroll
    for (int mt = 0; mt < 4; mt++){
        int row = m0 + wm*64 + mt*16 + g;
#pragma unroll
        for (int nt = 0; nt < 4; nt++){
            int col = n0 + wn*32 + nt*8 + 2*tg;
            if (col < N){
                float b0 = bias[col], b1 = bias[col+1];
                float v0 = acc[mt][nt][0] + b0;
                float v1 = acc[mt][nt][1] + b1;
                float v2 = acc[mt][nt][2] + b0;
                float v3 = acc[mt][nt][3] + b1;
                if (relu){
                    v0 = fmaxf(v0, 0.f); v1 = fmaxf(v1, 0.f);
                    v2 = fmaxf(v2, 0.f); v3 = fmaxf(v3, 0.f);
                }
                if (outBf){
                    bf16* C16 = (bf16*)Cv;
                    *(bf162*)&C16[(size_t)row*N + col]     = __floats2bfloat162_rn(v0, v1);
                    *(bf162*)&C16[(size_t)(row+8)*N + col] = __floats2bfloat162_rn(v2, v3);
                } else {
                    float* C = (float*)Cv;
                    *(float2*)&C[(size_t)row*N + col]     = make_float2(v0, v1);
                    *(float2*)&C[(size_t)(row+8)*N + col] = make_float2(v2, v3);
                }
            }
        }
    }
}

// ------------------- persistent bidirectional LSTM layer (R9 + reg-Whh + 128B slots) -----
// 128 blocks x 256 threads. dir = bx>>6, ns = bx&63. Block owns gate cols [ns*32,+32)
// (gate-interleaved) = hidden units [ns*8,+8). 8 warps as 4(m) x 2(n), warp tile 16x16.
#define WSB 520
__global__ __launch_bounds__(256) void lstm_layer(
    const bf16* __restrict__ pre,
    const bf16* __restrict__ whhF, const bf16* __restrict__ whhB,
    bf16* __restrict__ out, int gen0)
{
    extern __shared__ char smraw[];
    bf16* whh_s = (bf16*)smraw;                  // [32][WSB]
    bf16* h_s   = whh_s + 32*WSB;                // [64][WSB]
    bf16* pre_s = h_s + 64*WSB;                  // [2][64][32]
    float* G_s  = (float*)(pre_s + 2*64*32);     // [64][36]
    float* c_s  = G_s + 64*36;                   // [64][8]

    int tid = threadIdx.x;
    int warp = tid >> 5, lane = tid & 31;
    int wm = warp >> 1, wn = warp & 1;
    int g = lane >> 2, tg = lane & 3;
    int dir = blockIdx.x >> 6;
    int ns  = blockIdx.x & 63;
    int n0  = ns*32;
    int j0  = ns*8;
    const bf16* whh = dir ? whhB : whhF;
    int* slots = &d_slot[dir][0];

    // persistent Whh slice: 32 gate rows x 512
#pragma unroll
    for (int i = 0; i < 8; i++){
        int q = i*256 + tid;
        int r = q >> 6;
        int c = (q & 63) * 8;
        cp16(&whh_s[r*WSB + c], &whh[(n0 + r)*512 + c]);
    }
    cp_commit();
    for (int q = tid; q < 64*8; q += 256) c_s[q] = 0.f;
    cp_wait0();
    __syncthreads();

    // ldmatrix lane addresses
    int lrow = lane & 15;
    int lcol = (lane >> 4) * 16;
    unsigned hbase = (unsigned)__cvta_generic_to_shared(h_s);
    unsigned wbase = (unsigned)__cvta_generic_to_shared(whh_s);
    unsigned aAddr = hbase + (unsigned)((wm*16 + lrow)*WSB)*2u + lcol;
    unsigned bAddr = wbase + (unsigned)((wn*16 + lrow)*WSB)*2u + lcol;

    // register-resident Whh fragments: 32 k16-iters x 4 regs (loop-invariant)
    unsigned br[32][4];
#pragma unroll
    for (int k16 = 0; k16 < 32; k16++)
        ldsm4(br[k16][0], br[k16][1], br[k16][2], br[k16][3], bAddr + (unsigned)k16*32u);

    int ub = tid >> 2;            // batch 0..63
    int uu = (tid & 3)*2;         // first of 2 units
    int pr_ = tid >> 2, pc_ = (tid & 3)*8;   // pre staging coords

    // prefetch pre for step 0
    {
        int t0 = dir ? (SEQ-1) : 0;
        cp16(&pre_s[pr_*32 + pc_], &pre[((size_t)(pr_*SEQ + t0))*4096 + dir*2048 + n0 + pc_]);
        cp_commit();
    }

    for (int s = 0; s < SEQ; s++){
        int t  = dir ? (SEQ-1 - s) : s;
        int rp = s & 1;
        int wp = rp ^ 1;

        if (s > 0){
            const bf16* hsrc = d_hbuf + (size_t)(rp*2 + dir)*BATCH*HID;
            // chunk 0: k cols [0,256)
#pragma unroll
            for (int i = 0; i < 8; i++){
                int q = i*256 + tid;
                int r = q >> 5;
                int c = (q & 31) * 8;
                cp16(&h_s[r*WSB + c], &hsrc[r*HID + c]);
            }
            cp_commit();
            // chunk 1: k cols [256,512)
#pragma unroll
            for (int i = 0; i < 8; i++){
                int q = i*256 + tid;
                int r = q >> 5;
                int c = (q & 31) * 8 + 256;
                cp16(&h_s[r*WSB + c], &hsrc[r*HID + c]);
            }
            cp_commit();
        }
        // prefetch pre for step s+1
        {
            int sn = s + 1;
            if (sn < SEQ){
                int tn = dir ? (SEQ-1 - sn) : sn;
                bf16* pb = pre_s + (sn & 1)*2048;
                cp16(&pb[pr_*32 + pc_], &pre[((size_t)(pr_*SEQ + tn))*4096 + dir*2048 + n0 + pc_]);
            }
            cp_commit();
        }

        float acc[2][4];
#pragma unroll
        for (int b = 0; b < 2; b++)
#pragma unroll
            for (int c = 0; c < 4; c++) acc[b][c] = 0.f;

        if (s > 0){
            cp_wait2();             // h chunk0 ready (and pre(s) from last iter)
            __syncthreads();
#pragma unroll
            for (int k16 = 0; k16 < 16; k16++){
                unsigned off = (unsigned)k16 * 32u;
                unsigned a0,a1,a2,a3;
                ldsm4(a0,a1,a2,a3, aAddr + off);
                mma16r(acc[0], a0,a1,a2,a3, br[k16][0], br[k16][2]);
                mma16r(acc[1], a0,a1,a2,a3, br[k16][1], br[k16][3]);
            }
            cp_wait1();             // h chunk1 ready
            __syncthreads();
#pragma unroll
            for (int k16 = 16; k16 < 32; k16++){
                unsigned off = (unsigned)k16 * 32u;
                unsigned a0,a1,a2,a3;
                ldsm4(a0,a1,a2,a3, aAddr + off);
                mma16r(acc[0], a0,a1,a2,a3, br[k16][0], br[k16][2]);
                mma16r(acc[1], a0,a1,a2,a3, br[k16][1], br[k16][3]);
            }
        } else {
            cp_wait1();             // pre(0) ready
        }

        // dump accumulators (rows = batch, cols = gate)
        {
            int rr = wm*16 + g;
#pragma unroll
            for (int nt = 0; nt < 2; nt++){
                int cc = wn*16 + nt*8 + 2*tg;
                G_s[rr*36 + cc]        = acc[nt][0];
                G_s[rr*36 + cc + 1]    = acc[nt][1];
                G_s[(rr+8)*36 + cc]    = acc[nt][2];
                G_s[(rr+8)*36 + cc+1]  = acc[nt][3];
            }
        }
        __syncthreads();

        // gate update: thread -> batch ub, units uu..uu+1
        unsigned pk;
        {
            const bf16* pcur = pre_s + (s & 1)*2048;
            bf16* hdst = d_hbuf + (size_t)(wp*2 + dir)*BATCH*HID;
            float hv2[2];
#pragma unroll
            for (int k = 0; k < 2; k++){
                int u = uu + k;
                float4 Gv = *(float4*)&G_s[ub*36 + 4*u];
                bf162 pA = *(bf162*)&pcur[ub*32 + 4*u];
                bf162 pB = *(bf162*)&pcur[ub*32 + 4*u + 2];
                float iv = Gv.x + __low2float(pA);
                float fv = Gv.y + __high2float(pA);
                float gv = Gv.z + __low2float(pB);
                float ov = Gv.w + __high2float(pB);
                float co = c_s[ub*8 + u];
                float cn = fsig(fv)*co + fsig(iv)*ftanh(gv);
                hv2[k] = fsig(ov)*ftanh(cn);
                c_s[ub*8 + u] = cn;
            }
            bf162 p0 = __floats2bfloat162_rn(hv2[0], hv2[1]);
            pk = *(unsigned*)&p0;
            *(unsigned*)&hdst[ub*HID + j0 + uu] = pk;   // critical store only
        }

        // one-hop barrier: release -> out store overlaps poll -> acquire
        __syncthreads();
        int target = gen0 + s + 1;
        if (tid == 0) st_release(&slots[ns*32], target);
        *(unsigned*)&out[(size_t)(ub*SEQ + t)*H2 + dir*HID + j0 + uu] = pk;
        if (tid < 64){
            while (ld_acquire(&slots[tid*32]) < target) { }
        }
        __syncthreads();
    }
}

// ------------------- CRF: alpha' = m + log(exp(alpha-m) @ exp(T)) + em -------------------
__global__ void crf_kernel(const float* __restrict__ em, const int* __restrict__ tags,
                           const float* __restrict__ start, const float* __restrict__ endv,
                           const float* __restrict__ trans, float* __restrict__ v)
{
    __shared__ float E[NTAG*49];
    __shared__ float al[NTAG];
    __shared__ float p[NTAG];
    __shared__ float red[64];
    __shared__ float num_s;
    int b = blockIdx.x;
    int tid = threadIdx.x;
    const int* tg = tags + b*SEQ;
    const float* eb = em + b*SEQ*NTAG;

    for (int q = tid; q < NTAG*NTAG; q += 64){
        int i = q / NTAG, j = q - i*NTAG;
        E[i*49 + j] = __expf(trans[q]);
    }
    float part = 0.f;
    for (int t = tid; t < SEQ; t += 64){
        int tt = tg[t];
        part += eb[t*NTAG + tt];
        if (t < SEQ-1) part += trans[tt*NTAG + tg[t+1]];
    }
    red[tid] = part;
    if (tid < NTAG) al[tid] = start[tid] + eb[tid];
    __syncthreads();
    if (tid == 0){
        float s = 0.f;
        for (int i = 0; i < 64; i++) s += red[i];
        num_s = s + start[tg[0]] + endv[tg[SEQ-1]];
    }
    __syncthreads();

    for (int t = 1; t < SEQ; t++){
        if (tid < NTAG) p[tid] = __expf(al[tid] - al[0]);
        __syncthreads();
        float na = 0.f;
        if (tid < NTAG){
            float m0 = al[0];
            float ssum = 0.f;
#pragma unroll 8
            for (int i = 0; i < NTAG; i++) ssum += p[i] * E[i*49 + tid];
            na = m0 + __logf(ssum) + eb[t*NTAG + tid];
        }
        __syncthreads();
        if (tid < NTAG) al[tid] = na;
        __syncthreads();
    }

    if (tid == 0){
        float m = -1e30f;
        for (int j = 0; j < NTAG; j++) m = fmaxf(m, al[j] + endv[j]);
        float s = 0.f;
        for (int j = 0; j < NTAG; j++) s += __expf(al[j] + endv[j] - m);
        v[b] = num_s - (m + __logf(s));
    }
}

__global__ void final_reduce(const float* __restrict__ v, float* __restrict__ out){
    __shared__ float s[64];
    s[threadIdx.x] = v[threadIdx.x];
    __syncthreads();
    if (threadIdx.x == 0){
        float a = 0.f;
        for (int i = 0; i < 64; i++) a += s[i];
        out[0] = -(a / 64.f);
    }
}

// ------------------- launch -------------------
extern "C" void kernel_launch(void* const* d_in, const int* in_sizes, int n_in,
                              void* d_out, int out_size)
{
    const float* inputs = (const float*)d_in[0];
    const int*   tags   = (const int*)d_in[1];
    const float *Wih0f=(const float*)d_in[2],  *Whh0f=(const float*)d_in[3],
                *bih0f=(const float*)d_in[4],  *bhh0f=(const float*)d_in[5];
    const float *Wih0b=(const float*)d_in[6],  *Whh0b=(const float*)d_in[7],
                *bih0b=(const float*)d_in[8],  *bhh0b=(const float*)d_in[9];
    const float *Wih1f=(const float*)d_in[10], *Whh1f=(const float*)d_in[11],
                *bih1f=(const float*)d_in[12], *bhh1f=(const float*)d_in[13];
    const float *Wih1b=(const float*)d_in[14], *Whh1b=(const float*)d_in[15],
                *bih1b=(const float*)d_in[16], *bhh1b=(const float*)d_in[17];
    const float *gamma=(const float*)d_in[18], *beta=(const float*)d_in[19],
                *mean=(const float*)d_in[20],  *var=(const float*)d_in[21];
    const float *fc1w=(const float*)d_in[22], *fc1b=(const float*)d_in[23];
    const float *fc2w=(const float*)d_in[24], *fc2b=(const float*)d_in[25];
    const float *fc3w=(const float*)d_in[26], *fc3b=(const float*)d_in[27];
    const float *crfS=(const float*)d_in[28], *crfE=(const float*)d_in[29],
                *crfT=(const float*)d_in[30];

    bf16 *pInb,*pW0m,*pW1m,*pWh0f,*pWh0b,*pWh1f,*pWh1b;
    bf16 *pFc1w,*pFc2w,*pFc3w,*pX1,*pX2,*pF1,*pF2,*pPre;
    float *pB0m,*pB1m,*pFc1b,*pEm,*pV;
    cudaGetSymbolAddress((void**)&pInb, d_inb);
    cudaGetSymbolAddress((void**)&pW0m, d_W0m);
    cudaGetSymbolAddress((void**)&pW1m, d_W1m);
    cudaGetSymbolAddress((void**)&pWh0f, d_Wh0f);
    cudaGetSymbolAddress((void**)&pWh0b, d_Wh0b);
    cudaGetSymbolAddress((void**)&pWh1f, d_Wh1f);
    cudaGetSymbolAddress((void**)&pWh1b, d_Wh1b);
    cudaGetSymbolAddress((void**)&pB0m, d_b0m);
    cudaGetSymbolAddress((void**)&pB1m, d_b1m);
    cudaGetSymbolAddress((void**)&pFc1w, d_fc1wP);
    cudaGetSymbolAddress((void**)&pFc1b, d_fc1bP);
    cudaGetSymbolAddress((void**)&pFc2w, d_fc2wB);
    cudaGetSymbolAddress((void**)&pFc3w, d_fc3wB);
    cudaGetSymbolAddress((void**)&pPre, d_pre);
    cudaGetSymbolAddress((void**)&pX1, d_x1);
    cudaGetSymbolAddress((void**)&pX2, d_x2);
    cudaGetSymbolAddress((void**)&pF1, d_f1);
    cudaGetSymbolAddress((void**)&pF2, d_f2);
    cudaGetSymbolAddress((void**)&pEm, d_em);
    cudaGetSymbolAddress((void**)&pV, d_v);

    const int gemm_smem = 2*2*128*BRS*2;
    const int lstm_smem = (32*WSB + 64*WSB + 2*64*32)*2 + (64*36 + 64*8)*4;
    cudaFuncSetAttribute(gemm_bf16, cudaFuncAttributeMaxDynamicSharedMemorySize, gemm_smem);
    cudaFuncSetAttribute(lstm_layer, cudaFuncAttributeMaxDynamicSharedMemorySize, lstm_smem);

    prep_all<<<2048,256>>>(inputs, Wih0f, Wih0b, Whh0f, Whh0b, Wih1f, Wih1b, Whh1f, Whh1b,
                           bih0f, bhh0f, bih0b, bhh0b, bih1f, bhh1f, bih1b, bhh1b,
                           fc2w, fc3w);
    prep_fc<<<512,256>>>(fc1w, fc1b, gamma, beta, mean, var);
    gemm_bf16<<<dim3(32,128),256,gemm_smem>>>(pInb, pW0m, pB0m, pPre, MROWS, 4096, 256, 0, 1);
    lstm_layer<<<128,256,lstm_smem>>>(pPre, pWh0f, pWh0b, pX1, 0);
    gemm_bf16<<<dim3(32,128),256,gemm_smem>>>(pX1, pW1m, pB1m, pPre, MROWS, 4096, 1024, 0, 1);
    lstm_layer<<<128,256,lstm_smem>>>(pPre, pWh1f, pWh1b, pX2, 256);
    gemm_bf16<<<dim3(4,128),256,gemm_smem>>>(pX2, pFc1w, pFc1b, pF1, MROWS, 512, 1024, 1, 1);
    gemm_bf16<<<dim3(2,128),256,gemm_smem>>>(pF1, pFc2w, fc2b, pF2, MROWS, 256, 512, 1, 1);
    gemm_bf16<<<dim3(1,128),256,gemm_smem>>>(pF2, pFc3w, fc3b, pEm, MROWS, NTAG, 256, 0, 0);
    crf_kernel<<<64,64>>>(pEm, tags, crfS, crfE, crfT, pV);
    final_reduce<<<1,64>>>(pV, (float*)d_out);
}

// round 14
// speedup vs baseline: 1.7044x; 1.0447x over previous
#include <cuda_runtime.h>
#include <cuda_bf16.h>
#include <cstdint>

#define BATCH 64
#define SEQ   256
#define HID   512
#define NTAG  48
#define MROWS (BATCH*SEQ)     // 16384
#define G4    2048
#define H2    1024

typedef __nv_bfloat16 bf16;
typedef __nv_bfloat162 bf162;

// ------------------- static device scratch -------------------
__device__ bf16  d_inb[16384*256];
__device__ bf16  d_W0m[4096*256];
__device__ bf16  d_W1m[4096*1024];
__device__ bf16  d_Wh0f[2048*512];
__device__ bf16  d_Wh0b[2048*512];
__device__ bf16  d_Wh1f[2048*512];
__device__ bf16  d_Wh1b[2048*512];
__device__ float d_b0m[4096];
__device__ float d_b1m[4096];
__device__ bf16  d_fc1wP[512*1024];
__device__ float d_fc1bP[512];
__device__ bf16  d_fc2wB[256*512];
__device__ bf16  d_fc3wB[48*256];
__device__ bf16  d_pre[(size_t)16384*4096];
__device__ bf16  d_x1[16384*1024];
__device__ bf16  d_x2[16384*1024];
__device__ bf16  d_f1[16384*512];
__device__ bf16  d_f2[16384*256];
__device__ float d_em[16384*48];
__device__ bf16  d_hbuf[2*2*BATCH*HID];   // [parity][dir][b][j]
__device__ float d_v[64];
__device__ int   d_slot[2][2048];         // slot ns at index ns*32 (128B stride)

// ------------------- helpers -------------------
__device__ __forceinline__ void mma16r(float* c,
    unsigned a0, unsigned a1, unsigned a2, unsigned a3, unsigned b0, unsigned b1){
    asm volatile(
        "mma.sync.aligned.m16n8k16.row.col.f32.bf16.bf16.f32 "
        "{%0,%1,%2,%3}, {%4,%5,%6,%7}, {%8,%9}, {%0,%1,%2,%3};\n"
        : "+f"(c[0]), "+f"(c[1]), "+f"(c[2]), "+f"(c[3])
        : "r"(a0), "r"(a1), "r"(a2), "r"(a3), "r"(b0), "r"(b1));
}

__device__ __forceinline__ void ldsm4(unsigned& r0, unsigned& r1, unsigned& r2, unsigned& r3,
                                      unsigned addr){
    asm volatile("ldmatrix.sync.aligned.m8n8.x4.shared.b16 {%0,%1,%2,%3}, [%4];"
        : "=r"(r0), "=r"(r1), "=r"(r2), "=r"(r3) : "r"(addr));
}

__device__ __forceinline__ float fsig(float x){
    float t;
    asm("mul.f32 %0, %1, 0fBFB8AA3B;" : "=f"(t) : "f"(x));
    asm("ex2.approx.f32 %0, %0;" : "+f"(t));
    asm("add.f32 %0, %0, 0f3F800000;" : "+f"(t));
    asm("rcp.approx.f32 %0, %0;" : "+f"(t));
    return t;
}
__device__ __forceinline__ float ftanh(float x){
    float r; asm("tanh.approx.f32 %0, %1;" : "=f"(r) : "f"(x)); return r;
}

__device__ __forceinline__ void st_release(int* addr, int v){
    asm volatile("st.release.gpu.global.s32 [%0], %1;" :: "l"(addr), "r"(v) : "memory");
}
__device__ __forceinline__ int ld_acquire(const int* addr){
    int v;
    asm volatile("ld.acquire.gpu.global.s32 %0, [%1];" : "=r"(v) : "l"(addr) : "memory");
    return v;
}

__device__ __forceinline__ void cp16(void* smem, const void* gmem){
    unsigned sa = (unsigned)__cvta_generic_to_shared(smem);
    asm volatile("cp.async.cg.shared.global [%0], [%1], 16;" :: "r"(sa), "l"(gmem));
}
__device__ __forceinline__ void cp16z(void* smem, const void* gmem, int pred){
    unsigned sa = (unsigned)__cvta_generic_to_shared(smem);
    int bytes = pred ? 16 : 0;
    asm volatile("cp.async.cg.shared.global [%0], [%1], 16, %2;" :: "r"(sa), "l"(gmem), "r"(bytes));
}
__device__ __forceinline__ void cp_commit(){ asm volatile("cp.async.commit_group;"); }
__device__ __forceinline__ void cp_wait0(){ asm volatile("cp.async.wait_group 0;"); }
__device__ __forceinline__ void cp_wait1(){ asm volatile("cp.async.wait_group 1;"); }
__device__ __forceinline__ void cp_wait2(){ asm volatile("cp.async.wait_group 2;"); }

// ------------------- prep -------------------
// gate permutation (R9): out row n' -> src row (n'&3)*512 + (n'>>2)
__global__ void prep_all(
    const float* __restrict__ inputs,
    const float* __restrict__ Wih0f, const float* __restrict__ Wih0b,
    const float* __restrict__ Whh0f, const float* __restrict__ Whh0b,
    const float* __restrict__ Wih1f, const float* __restrict__ Wih1b,
    const float* __restrict__ Whh1f, const float* __restrict__ Whh1b,
    const float* __restrict__ bih0f, const float* __restrict__ bhh0f,
    const float* __restrict__ bih0b, const float* __restrict__ bhh0b,
    const float* __restrict__ bih1f, const float* __restrict__ bhh1f,
    const float* __restrict__ bih1b, const float* __restrict__ bhh1b,
    const float* __restrict__ fc2w, const float* __restrict__ fc3w)
{
    const int NIN = 16384*256;
    const int NW0 = 4096*256;
    const int NW1 = 4096*1024;
    const int NWH = 2048*512;
    const int e0 = NIN;
    const int e1 = e0 + NW0;
    const int e2 = e1 + NW1;
    const int e3 = e2 + 4*NWH;
    const int e4 = e3 + 4096;
    const int e5 = e4 + 4096;
    const int e6 = e5 + 256*512;
    const int e7 = e6 + 48*256;
    const int total = e7 + 4096;        // ctrl: 4096 slot ints
    int stride = gridDim.x * blockDim.x;
    for (int i = blockIdx.x*blockDim.x + threadIdx.x; i < total; i += stride){
        if (i < e0){
            d_inb[i] = __float2bfloat16_rn(inputs[i]);
        } else if (i < e1){
            int j = i - e0;
            int np = j >> 8, k = j & 255;
            int np2 = np & 2047;
            int sr = (np2 & 3)*512 + (np2 >> 2);
            const float* src = (np < 2048) ? Wih0f : Wih0b;
            d_W0m[j] = __float2bfloat16_rn(src[sr*256 + k]);
        } else if (i < e2){
            int j = i - e1;
            int np = j >> 10, k = j & 1023;
            int np2 = np & 2047;
            int sr = (np2 & 3)*512 + (np2 >> 2);
            const float* src = (np < 2048) ? Wih1f : Wih1b;
            d_W1m[j] = __float2bfloat16_rn(src[sr*1024 + k]);
        } else if (i < e3){
            int j = i - e2;
            int arr = j / NWH;
            int jj = j - arr*NWH;
            int np = jj >> 9, k = jj & 511;
            int sr = (np & 3)*512 + (np >> 2);
            const float* src = (arr==0)?Whh0f:(arr==1)?Whh0b:(arr==2)?Whh1f:Whh1b;
            bf16* dst = (arr==0)?d_Wh0f:(arr==1)?d_Wh0b:(arr==2)?d_Wh1f:d_Wh1b;
            dst[jj] = __float2bfloat16_rn(src[sr*512 + k]);
        } else if (i < e4){
            int np = i - e3;
            int np2 = np & 2047;
            int sr = (np2 & 3)*512 + (np2 >> 2);
            d_b0m[np] = (np < 2048) ? (bih0f[sr] + bhh0f[sr]) : (bih0b[sr] + bhh0b[sr]);
        } else if (i < e5){
            int np = i - e4;
            int np2 = np & 2047;
            int sr = (np2 & 3)*512 + (np2 >> 2);
            d_b1m[np] = (np < 2048) ? (bih1f[sr] + bhh1f[sr]) : (bih1b[sr] + bhh1b[sr]);
        } else if (i < e6){
            int j = i - e5;
            d_fc2wB[j] = __float2bfloat16_rn(fc2w[j]);
        } else if (i < e7){
            int j = i - e6;
            d_fc3wB[j] = __float2bfloat16_rn(fc3w[j]);
        } else {
            ((int*)d_slot)[i - e7] = 0;
        }
    }
}

// fold BN into fc1
__global__ void prep_fc(const float* __restrict__ fc1w, const float* __restrict__ fc1b,
                        const float* __restrict__ gamma, const float* __restrict__ beta,
                        const float* __restrict__ mean, const float* __restrict__ var)
{
    __shared__ float red[256];
    int r = blockIdx.x;
    int tid = threadIdx.x;
    float part = 0.f;
    for (int c = tid; c < 1024; c += 256){
        float sc = gamma[c] * rsqrtf(var[c] + 1e-5f);
        float tc = beta[c] - mean[c]*sc;
        float w = fc1w[r*1024 + c];
        d_fc1wP[r*1024 + c] = __float2bfloat16_rn(w * sc);
        part += w * tc;
    }
    red[tid] = part;
    __syncthreads();
    for (int off = 128; off > 0; off >>= 1){
        if (tid < off) red[tid] += red[tid + off];
        __syncthreads();
    }
    if (tid == 0) d_fc1bP[r] = fc1b[r] + red[0];
}

// ------------------- bf16 GEMM: C = A(MxK) @ W(NxK)^T + bias (ldmatrix) -------------------
#define BRS 40
__global__ __launch_bounds__(256) void gemm_bf16(
    const bf16* __restrict__ A, const bf16* __restrict__ W,
    const float* __restrict__ bias, void* __restrict__ Cv,
    int M, int N, int K, int relu, int outBf)
{
    extern __shared__ bf16 smb[];
    bf16* As = smb;
    bf16* Bs = smb + 2*128*BRS;
    int tid  = threadIdx.x;
    int warp = tid >> 5, lane = tid & 31;
    int wm = warp >> 2, wn = warp & 3;
    int g = lane >> 2, tg = lane & 3;
    int m0 = blockIdx.y*128, n0 = blockIdx.x*128;

    float acc[4][4][4];
#pragma unroll
    for (int a = 0; a < 4; a++)
#pragma unroll
        for (int b = 0; b < 4; b++)
#pragma unroll
            for (int c = 0; c < 4; c++) acc[a][b][c] = 0.f;

    int KT = K >> 5;

    auto stage = [&](int kt, int bb){
        const bf16* Ag = A + (size_t)m0*K + kt*32;
#pragma unroll
        for (int i = 0; i < 2; i++){
            int q = i*256 + tid;
            int r = q >> 2;
            int c = (q & 3) * 8;
            cp16(&As[bb*128*BRS + r*BRS + c], Ag + (size_t)r*K + c);
        }
        const bf16* Wg = W + kt*32;
#pragma unroll
        for (int i = 0; i < 2; i++){
            int q = i*256 + tid;
            int r = q >> 2;
            int c = (q & 3) * 8;
            int nr = n0 + r;
            int nc = nr < N ? nr : 0;
            cp16z(&Bs[bb*128*BRS + r*BRS + c], Wg + (size_t)nc*K + c, nr < N);
        }
        cp_commit();
    };

    stage(0, 0);
    if (KT > 1) stage(1, 1);

    // ldmatrix lane addressing (same validated pattern as lstm_layer)
    int lrow = lane & 15;
    int lcol = (lane >> 4) * 16;                 // byte offset into 32B k-slab
    unsigned Abase = (unsigned)__cvta_generic_to_shared(As);
    unsigned Bbase = (unsigned)__cvta_generic_to_shared(Bs);
    const unsigned BUFB = 128*BRS*2;             // bytes per buffer
    unsigned aW = (unsigned)((wm*64 + lrow)*BRS)*2u + lcol;
    unsigned bW = (unsigned)((wn*32 + lrow)*BRS)*2u + lcol;

    for (int kt = 0; kt < KT; kt++){
        if (kt < KT-1) cp_wait1(); else cp_wait0();
        __syncthreads();
        int bb = kt & 1;
        unsigned aAd = Abase + (unsigned)bb*BUFB + aW;
        unsigned bAd = Bbase + (unsigned)bb*BUFB + bW;
#pragma unroll
        for (int kk = 0; kk < 2; kk++){
            unsigned ko = (unsigned)kk * 32u;
            unsigned af[4][4];
#pragma unroll
            for (int mt = 0; mt < 4; mt++)
                ldsm4(af[mt][0], af[mt][1], af[mt][2], af[mt][3],
                      aAd + (unsigned)(mt*16*BRS)*2u + ko);
            unsigned b0,b1,b2,b3, c0,c1,c2,c3;
            ldsm4(b0,b1,b2,b3, bAd + ko);
            ldsm4(c0,c1,c2,c3, bAd + (unsigned)(16*BRS)*2u + ko);
#pragma unroll
            for (int mt = 0; mt < 4; mt++){
                mma16r(acc[mt][0], af[mt][0], af[mt][1], af[mt][2], af[mt][3], b0, b2);
                mma16r(acc[mt][1], af[mt][0], af[mt][1], af[mt][2], af[mt][3], b1, b3);
                mma16r(acc[mt][2], af[mt][0], af[mt][1], af[mt][2], af[mt][3], c0, c2);
                mma16r(acc[mt][3], af[mt][0], af[mt][1], af[mt][2], af[mt][3], c1, c3);
            }
        }
        __syncthreads();
        if (kt + 2 < KT) stage(kt+2, bb);
    }

#pragma unroll
    for (int mt = 0; mt < 4; mt++){
        int row = m0 + wm*64 + mt*16 + g;
#pragma unroll
        for (int nt = 0; nt < 4; nt++){
            int col = n0 + wn*32 + nt*8 + 2*tg;
            if (col < N){
                float b0 = bias[col], b1 = bias[col+1];
                float v0 = acc[mt][nt][0] + b0;
                float v1 = acc[mt][nt][1] + b1;
                float v2 = acc[mt][nt][2] + b0;
                float v3 = acc[mt][nt][3] + b1;
                if (relu){
                    v0 = fmaxf(v0, 0.f); v1 = fmaxf(v1, 0.f);
                    v2 = fmaxf(v2, 0.f); v3 = fmaxf(v3, 0.f);
                }
                if (outBf){
                    bf16* C16 = (bf16*)Cv;
                    *(bf162*)&C16[(size_t)row*N + col]     = __floats2bfloat162_rn(v0, v1);
                    *(bf162*)&C16[(size_t)(row+8)*N + col] = __floats2bfloat162_rn(v2, v3);
                } else {
                    float* C = (float*)Cv;
                    *(float2*)&C[(size_t)row*N + col]     = make_float2(v0, v1);
                    *(float2*)&C[(size_t)(row+8)*N + col] = make_float2(v2, v3);
                }
            }
        }
    }
}

// ------------------- persistent bidirectional LSTM layer (R13) -------------------
#define WSB 520
__global__ __launch_bounds__(256) void lstm_layer(
    const bf16* __restrict__ pre,
    const bf16* __restrict__ whhF, const bf16* __restrict__ whhB,
    bf16* __restrict__ out, int gen0)
{
    extern __shared__ char smraw[];
    bf16* whh_s = (bf16*)smraw;                  // [32][WSB]
    bf16* h_s   = whh_s + 32*WSB;                // [64][WSB]
    bf16* pre_s = h_s + 64*WSB;                  // [2][64][32]
    float* G_s  = (float*)(pre_s + 2*64*32);     // [64][36]
    float* c_s  = G_s + 64*36;                   // [64][8]

    int tid = threadIdx.x;
    int warp = tid >> 5, lane = tid & 31;
    int wm = warp >> 1, wn = warp & 1;
    int g = lane >> 2, tg = lane & 3;
    int dir = blockIdx.x >> 6;
    int ns  = blockIdx.x & 63;
    int n0  = ns*32;
    int j0  = ns*8;
    const bf16* whh = dir ? whhB : whhF;
    int* slots = &d_slot[dir][0];

    // persistent Whh slice: 32 gate rows x 512
#pragma unroll
    for (int i = 0; i < 8; i++){
        int q = i*256 + tid;
        int r = q >> 6;
        int c = (q & 63) * 8;
        cp16(&whh_s[r*WSB + c], &whh[(n0 + r)*512 + c]);
    }
    cp_commit();
    for (int q = tid; q < 64*8; q += 256) c_s[q] = 0.f;
    cp_wait0();
    __syncthreads();

    // ldmatrix lane addresses
    int lrow = lane & 15;
    int lcol = (lane >> 4) * 16;
    unsigned hbase = (unsigned)__cvta_generic_to_shared(h_s);
    unsigned wbase = (unsigned)__cvta_generic_to_shared(whh_s);
    unsigned aAddr = hbase + (unsigned)((wm*16 + lrow)*WSB)*2u + lcol;
    unsigned bAddr = wbase + (unsigned)((wn*16 + lrow)*WSB)*2u + lcol;

    // register-resident Whh fragments: 32 k16-iters x 4 regs (loop-invariant)
    unsigned br[32][4];
#pragma unroll
    for (int k16 = 0; k16 < 32; k16++)
        ldsm4(br[k16][0], br[k16][1], br[k16][2], br[k16][3], bAddr + (unsigned)k16*32u);

    int ub = tid >> 2;            // batch 0..63
    int uu = (tid & 3)*2;         // first of 2 units
    int pr_ = tid >> 2, pc_ = (tid & 3)*8;   // pre staging coords

    // prefetch pre for step 0
    {
        int t0 = dir ? (SEQ-1) : 0;
        cp16(&pre_s[pr_*32 + pc_], &pre[((size_t)(pr_*SEQ + t0))*4096 + dir*2048 + n0 + pc_]);
        cp_commit();
    }

    for (int s = 0; s < SEQ; s++){
        int t  = dir ? (SEQ-1 - s) : s;
        int rp = s & 1;
        int wp = rp ^ 1;

        if (s > 0){
            const bf16* hsrc = d_hbuf + (size_t)(rp*2 + dir)*BATCH*HID;
#pragma unroll
            for (int i = 0; i < 8; i++){
                int q = i*256 + tid;
                int r = q >> 5;
                int c = (q & 31) * 8;
                cp16(&h_s[r*WSB + c], &hsrc[r*HID + c]);
            }
            cp_commit();
#pragma unroll
            for (int i = 0; i < 8; i++){
                int q = i*256 + tid;
                int r = q >> 5;
                int c = (q & 31) * 8 + 256;
                cp16(&h_s[r*WSB + c], &hsrc[r*HID + c]);
            }
            cp_commit();
        }
        {
            int sn = s + 1;
            if (sn < SEQ){
                int tn = dir ? (SEQ-1 - sn) : sn;
                bf16* pb = pre_s + (sn & 1)*2048;
                cp16(&pb[pr_*32 + pc_], &pre[((size_t)(pr_*SEQ + tn))*4096 + dir*2048 + n0 + pc_]);
            }
            cp_commit();
        }

        float acc[2][4];
#pragma unroll
        for (int b = 0; b < 2; b++)
#pragma unroll
            for (int c = 0; c < 4; c++) acc[b][c] = 0.f;

        if (s > 0){
            cp_wait2();
            __syncthreads();
#pragma unroll
            for (int k16 = 0; k16 < 16; k16++){
                unsigned off = (unsigned)k16 * 32u;
                unsigned a0,a1,a2,a3;
                ldsm4(a0,a1,a2,a3, aAddr + off);
                mma16r(acc[0], a0,a1,a2,a3, br[k16][0], br[k16][2]);
                mma16r(acc[1], a0,a1,a2,a3, br[k16][1], br[k16][3]);
            }
            cp_wait1();
            __syncthreads();
#pragma unroll
            for (int k16 = 16; k16 < 32; k16++){
                unsigned off = (unsigned)k16 * 32u;
                unsigned a0,a1,a2,a3;
                ldsm4(a0,a1,a2,a3, aAddr + off);
                mma16r(acc[0], a0,a1,a2,a3, br[k16][0], br[k16][2]);
                mma16r(acc[1], a0,a1,a2,a3, br[k16][1], br[k16][3]);
            }
        } else {
            cp_wait1();
        }

        // dump accumulators (rows = batch, cols = gate)
        {
            int rr = wm*16 + g;
#pragma unroll
            for (int nt = 0; nt < 2; nt++){
                int cc = wn*16 + nt*8 + 2*tg;
                G_s[rr*36 + cc]        = acc[nt][0];
                G_s[rr*36 + cc + 1]    = acc[nt][1];
                G_s[(rr+8)*36 + cc]    = acc[nt][2];
                G_s[(rr+8)*36 + cc+1]  = acc[nt][3];
            }
        }
        __syncthreads();

        // gate update: thread -> batch ub, units uu..uu+1
        unsigned pk;
        {
            const bf16* pcur = pre_s + (s & 1)*2048;
            bf16* hdst = d_hbuf + (size_t)(wp*2 + dir)*BATCH*HID;
            float hv2[2];
#pragma unroll
            for (int k = 0; k < 2; k++){
                int u = uu + k;
                float4 Gv = *(float4*)&G_s[ub*36 + 4*u];
                bf162 pA = *(bf162*)&pcur[ub*32 + 4*u];
                bf162 pB = *(bf162*)&pcur[ub*32 + 4*u + 2];
                float iv = Gv.x + __low2float(pA);
                float fv = Gv.y + __high2float(pA);
                float gv = Gv.z + __low2float(pB);
                float ov = Gv.w + __high2float(pB);
                float co = c_s[ub*8 + u];
                float cn = fsig(fv)*co + fsig(iv)*ftanh(gv);
                hv2[k] = fsig(ov)*ftanh(cn);
                c_s[ub*8 + u] = cn;
            }
            bf162 p0 = __floats2bfloat162_rn(hv2[0], hv2[1]);
            pk = *(unsigned*)&p0;
            *(unsigned*)&hdst[ub*HID + j0 + uu] = pk;
        }

        // one-hop barrier: release -> out store overlaps poll -> acquire
        __syncthreads();
        int target = gen0 + s + 1;
        if (tid == 0) st_release(&slots[ns*32], target);
        *(unsigned*)&out[(size_t)(ub*SEQ + t)*H2 + dir*HID + j0 + uu] = pk;
        if (tid < 64){
            while (ld_acquire(&slots[tid*32]) < target) { }
        }
        __syncthreads();
    }
}

// ------------------- CRF -------------------
__global__ void crf_kernel(const float* __restrict__ em, const int* __restrict__ tags,
                           const float* __restrict__ start, const float* __restrict__ endv,
                           const float* __restrict__ trans, float* __restrict__ v)
{
    __shared__ float E[NTAG*49];
    __shared__ float al[NTAG];
    __shared__ float p[NTAG];
    __shared__ float red[64];
    __shared__ float num_s;
    int b = blockIdx.x;
    int tid = threadIdx.x;
    const int* tg = tags + b*SEQ;
    const float* eb = em + b*SEQ*NTAG;

    for (int q = tid; q < NTAG*NTAG; q += 64){
        int i = q / NTAG, j = q - i*NTAG;
        E[i*49 + j] = __expf(trans[q]);
    }
    float part = 0.f;
    for (int t = tid; t < SEQ; t += 64){
        int tt = tg[t];
        part += eb[t*NTAG + tt];
        if (t < SEQ-1) part += trans[tt*NTAG + tg[t+1]];
    }
    red[tid] = part;
    if (tid < NTAG) al[tid] = start[tid] + eb[tid];
    __syncthreads();
    if (tid == 0){
        float s = 0.f;
        for (int i = 0; i < 64; i++) s += red[i];
        num_s = s + start[tg[0]] + endv[tg[SEQ-1]];
    }
    __syncthreads();

    for (int t = 1; t < SEQ; t++){
        if (tid < NTAG) p[tid] = __expf(al[tid] - al[0]);
        __syncthreads();
        float na = 0.f;
        if (tid < NTAG){
            float m0 = al[0];
            float ssum = 0.f;
#pragma unroll 8
            for (int i = 0; i < NTAG; i++) ssum += p[i] * E[i*49 + tid];
            na = m0 + __logf(ssum) + eb[t*NTAG + tid];
        }
        __syncthreads();
        if (tid < NTAG) al[tid] = na;
        __syncthreads();
    }

    if (tid == 0){
        float m = -1e30f;
        for (int j = 0; j < NTAG; j++) m = fmaxf(m, al[j] + endv[j]);
        float s = 0.f;
        for (int j = 0; j < NTAG; j++) s += __expf(al[j] + endv[j] - m);
        v[b] = num_s - (m + __logf(s));
    }
}

__global__ void final_reduce(const float* __restrict__ v, float* __restrict__ out){
    __shared__ float s[64];
    s[threadIdx.x] = v[threadIdx.x];
    __syncthreads();
    if (threadIdx.x == 0){
        float a = 0.f;
        for (int i = 0; i < 64; i++) a += s[i];
        out[0] = -(a / 64.f);
    }
}

// ------------------- launch -------------------
extern "C" void kernel_launch(void* const* d_in, const int* in_sizes, int n_in,
                              void* d_out, int out_size)
{
    const float* inputs = (const float*)d_in[0];
    const int*   tags   = (const int*)d_in[1];
    const float *Wih0f=(const float*)d_in[2],  *Whh0f=(const float*)d_in[3],
                *bih0f=(const float*)d_in[4],  *bhh0f=(const float*)d_in[5];
    const float *Wih0b=(const float*)d_in[6],  *Whh0b=(const float*)d_in[7],
                *bih0b=(const float*)d_in[8],  *bhh0b=(const float*)d_in[9];
    const float *Wih1f=(const float*)d_in[10], *Whh1f=(const float*)d_in[11],
                *bih1f=(const float*)d_in[12], *bhh1f=(const float*)d_in[13];
    const float *Wih1b=(const float*)d_in[14], *Whh1b=(const float*)d_in[15],
                *bih1b=(const float*)d_in[16], *bhh1b=(const float*)d_in[17];
    const float *gamma=(const float*)d_in[18], *beta=(const float*)d_in[19],
                *mean=(const float*)d_in[20],  *var=(const float*)d_in[21];
    const float *fc1w=(const float*)d_in[22], *fc1b=(const float*)d_in[23];
    const float *fc2w=(const float*)d_in[24], *fc2b=(const float*)d_in[25];
    const float *fc3w=(const float*)d_in[26], *fc3b=(const float*)d_in[27];
    const float *crfS=(const float*)d_in[28], *crfE=(const float*)d_in[29],
                *crfT=(const float*)d_in[30];

    bf16 *pInb,*pW0m,*pW1m,*pWh0f,*pWh0b,*pWh1f,*pWh1b;
    bf16 *pFc1w,*pFc2w,*pFc3w,*pX1,*pX2,*pF1,*pF2,*pPre;
    float *pB0m,*pB1m,*pFc1b,*pEm,*pV;
    cudaGetSymbolAddress((void**)&pInb, d_inb);
    cudaGetSymbolAddress((void**)&pW0m, d_W0m);
    cudaGetSymbolAddress((void**)&pW1m, d_W1m);
    cudaGetSymbolAddress((void**)&pWh0f, d_Wh0f);
    cudaGetSymbolAddress((void**)&pWh0b, d_Wh0b);
    cudaGetSymbolAddress((void**)&pWh1f, d_Wh1f);
    cudaGetSymbolAddress((void**)&pWh1b, d_Wh1b);
    cudaGetSymbolAddress((void**)&pB0m, d_b0m);
    cudaGetSymbolAddress((void**)&pB1m, d_b1m);
    cudaGetSymbolAddress((void**)&pFc1w, d_fc1wP);
    cudaGetSymbolAddress((void**)&pFc1b, d_fc1bP);
    cudaGetSymbolAddress((void**)&pFc2w, d_fc2wB);
    cudaGetSymbolAddress((void**)&pFc3w, d_fc3wB);
    cudaGetSymbolAddress((void**)&pPre, d_pre);
    cudaGetSymbolAddress((void**)&pX1, d_x1);
    cudaGetSymbolAddress((void**)&pX2, d_x2);
    cudaGetSymbolAddress((void**)&pF1, d_f1);
    cudaGetSymbolAddress((void**)&pF2, d_f2);
    cudaGetSymbolAddress((void**)&pEm, d_em);
    cudaGetSymbolAddress((void**)&pV, d_v);

    const int gemm_smem = 2*2*128*BRS*2;
    const int lstm_smem = (32*WSB + 64*WSB + 2*64*32)*2 + (64*36 + 64*8)*4;
    cudaFuncSetAttribute(gemm_bf16, cudaFuncAttributeMaxDynamicSharedMemorySize, gemm_smem);
    cudaFuncSetAttribute(lstm_layer, cudaFuncAttributeMaxDynamicSharedMemorySize, lstm_smem);

    prep_all<<<2048,256>>>(inputs, Wih0f, Wih0b, Whh0f, Whh0b, Wih1f, Wih1b, Whh1f, Whh1b,
                           bih0f, bhh0f, bih0b, bhh0b, bih1f, bhh1f, bih1b, bhh1b,
                           fc2w, fc3w);
    prep_fc<<<512,256>>>(fc1w, fc1b, gamma, beta, mean, var);
    gemm_bf16<<<dim3(32,128),256,gemm_smem>>>(pInb, pW0m, pB0m, pPre, MROWS, 4096, 256, 0, 1);
    lstm_layer<<<128,256,lstm_smem>>>(pPre, pWh0f, pWh0b, pX1, 0);
    gemm_bf16<<<dim3(32,128),256,gemm_smem>>>(pX1, pW1m, pB1m, pPre, MROWS, 4096, 1024, 0, 1);
    lstm_layer<<<128,256,lstm_smem>>>(pPre, pWh1f, pWh1b, pX2, 256);
    gemm_bf16<<<dim3(4,128),256,gemm_smem>>>(pX2, pFc1w, pFc1b, pF1, MROWS, 512, 1024, 1, 1);
    gemm_bf16<<<dim3(2,128),256,gemm_smem>>>(pF1, pFc2w, fc2b, pF2, MROWS, 256, 512, 1, 1);
    gemm_bf16<<<dim3(1,128),256,gemm_smem>>>(pF2, pFc3w, fc3b, pEm, MROWS, NTAG, 256, 0, 0);
    crf_kernel<<<64,64>>>(pEm, tags, crfS, crfE, crfT, pV);
    final_reduce<<<1,64>>>(pV, (float*)d_out);
}

// round 15
// speedup vs baseline: 1.7594x; 1.0323x over previous
#include <cuda_runtime.h>
#include <cuda_bf16.h>
#include <cstdint>

#define BATCH 64
#define SEQ   256
#define HID   512
#define NTAG  48
#define MROWS (BATCH*SEQ)     // 16384
#define G4    2048
#define H2    1024

typedef __nv_bfloat16 bf16;
typedef __nv_bfloat162 bf162;

// ------------------- static device scratch -------------------
__device__ bf16  d_inb[16384*256];
__device__ bf16  d_W0m[4096*256];
__device__ bf16  d_W1m[4096*1024];
__device__ bf16  d_Wh0f[2048*512];
__device__ bf16  d_Wh0b[2048*512];
__device__ bf16  d_Wh1f[2048*512];
__device__ bf16  d_Wh1b[2048*512];
__device__ float d_b0m[4096];
__device__ float d_b1m[4096];
__device__ bf16  d_fc1wP[512*1024];
__device__ float d_fc1bP[512];
__device__ bf16  d_fc2wB[256*512];
__device__ bf16  d_fc3wB[48*256];
__device__ bf16  d_pre[(size_t)16384*4096];
__device__ bf16  d_x1[16384*1024];
__device__ bf16  d_x2[16384*1024];
__device__ bf16  d_f1[16384*512];
__device__ bf16  d_f2[16384*256];
__device__ float d_em[16384*48];
__device__ bf16  d_hbuf[2*2*BATCH*HID];   // [parity][dir][b][j]
__device__ float d_v[64];
__device__ int   d_slot[2][2048];         // slot ns at index ns*32 (128B stride)

// ------------------- helpers -------------------
__device__ __forceinline__ void mma16r(float* c,
    unsigned a0, unsigned a1, unsigned a2, unsigned a3, unsigned b0, unsigned b1){
    asm volatile(
        "mma.sync.aligned.m16n8k16.row.col.f32.bf16.bf16.f32 "
        "{%0,%1,%2,%3}, {%4,%5,%6,%7}, {%8,%9}, {%0,%1,%2,%3};\n"
        : "+f"(c[0]), "+f"(c[1]), "+f"(c[2]), "+f"(c[3])
        : "r"(a0), "r"(a1), "r"(a2), "r"(a3), "r"(b0), "r"(b1));
}

__device__ __forceinline__ void ldsm4(unsigned& r0, unsigned& r1, unsigned& r2, unsigned& r3,
                                      unsigned addr){
    asm volatile("ldmatrix.sync.aligned.m8n8.x4.shared.b16 {%0,%1,%2,%3}, [%4];"
        : "=r"(r0), "=r"(r1), "=r"(r2), "=r"(r3) : "r"(addr));
}

__device__ __forceinline__ float fsig(float x){
    float t;
    asm("mul.f32 %0, %1, 0fBFB8AA3B;" : "=f"(t) : "f"(x));
    asm("ex2.approx.f32 %0, %0;" : "+f"(t));
    asm("add.f32 %0, %0, 0f3F800000;" : "+f"(t));
    asm("rcp.approx.f32 %0, %0;" : "+f"(t));
    return t;
}
__device__ __forceinline__ float ftanh(float x){
    float r; asm("tanh.approx.f32 %0, %1;" : "=f"(r) : "f"(x)); return r;
}

__device__ __forceinline__ void st_release(int* addr, int v){
    asm volatile("st.release.gpu.global.s32 [%0], %1;" :: "l"(addr), "r"(v) : "memory");
}
__device__ __forceinline__ int ld_acquire(const int* addr){
    int v;
    asm volatile("ld.acquire.gpu.global.s32 %0, [%1];" : "=r"(v) : "l"(addr) : "memory");
    return v;
}

__device__ __forceinline__ void cp16(void* smem, const void* gmem){
    unsigned sa = (unsigned)__cvta_generic_to_shared(smem);
    asm volatile("cp.async.cg.shared.global [%0], [%1], 16;" :: "r"(sa), "l"(gmem));
}
__device__ __forceinline__ void cp16z(void* smem, const void* gmem, int pred){
    unsigned sa = (unsigned)__cvta_generic_to_shared(smem);
    int bytes = pred ? 16 : 0;
    asm volatile("cp.async.cg.shared.global [%0], [%1], 16, %2;" :: "r"(sa), "l"(gmem), "r"(bytes));
}
__device__ __forceinline__ void cp_commit(){ asm volatile("cp.async.commit_group;"); }
__device__ __forceinline__ void cp_wait0(){ asm volatile("cp.async.wait_group 0;"); }
__device__ __forceinline__ void cp_wait1(){ asm volatile("cp.async.wait_group 1;"); }
__device__ __forceinline__ void cp_wait2(){ asm volatile("cp.async.wait_group 2;"); }

// ------------------- prep -------------------
// gate permutation (R9): out row n' -> src row (n'&3)*512 + (n'>>2)
__global__ void prep_all(
    const float* __restrict__ inputs,
    const float* __restrict__ Wih0f, const float* __restrict__ Wih0b,
    const float* __restrict__ Whh0f, const float* __restrict__ Whh0b,
    const float* __restrict__ Wih1f, const float* __restrict__ Wih1b,
    const float* __restrict__ Whh1f, const float* __restrict__ Whh1b,
    const float* __restrict__ bih0f, const float* __restrict__ bhh0f,
    const float* __restrict__ bih0b, const float* __restrict__ bhh0b,
    const float* __restrict__ bih1f, const float* __restrict__ bhh1f,
    const float* __restrict__ bih1b, const float* __restrict__ bhh1b,
    const float* __restrict__ fc2w, const float* __restrict__ fc3w)
{
    const int NIN = 16384*256;
    const int NW0 = 4096*256;
    const int NW1 = 4096*1024;
    const int NWH = 2048*512;
    const int e0 = NIN;
    const int e1 = e0 + NW0;
    const int e2 = e1 + NW1;
    const int e3 = e2 + 4*NWH;
    const int e4 = e3 + 4096;
    const int e5 = e4 + 4096;
    const int e6 = e5 + 256*512;
    const int e7 = e6 + 48*256;
    const int total = e7 + 4096;
    int stride = gridDim.x * blockDim.x;
    for (int i = blockIdx.x*blockDim.x + threadIdx.x; i < total; i += stride){
        if (i < e0){
            d_inb[i] = __float2bfloat16_rn(inputs[i]);
        } else if (i < e1){
            int j = i - e0;
            int np = j >> 8, k = j & 255;
            int np2 = np & 2047;
            int sr = (np2 & 3)*512 + (np2 >> 2);
            const float* src = (np < 2048) ? Wih0f : Wih0b;
            d_W0m[j] = __float2bfloat16_rn(src[sr*256 + k]);
        } else if (i < e2){
            int j = i - e1;
            int np = j >> 10, k = j & 1023;
            int np2 = np & 2047;
            int sr = (np2 & 3)*512 + (np2 >> 2);
            const float* src = (np < 2048) ? Wih1f : Wih1b;
            d_W1m[j] = __float2bfloat16_rn(src[sr*1024 + k]);
        } else if (i < e3){
            int j = i - e2;
            int arr = j / NWH;
            int jj = j - arr*NWH;
            int np = jj >> 9, k = jj & 511;
            int sr = (np & 3)*512 + (np >> 2);
            const float* src = (arr==0)?Whh0f:(arr==1)?Whh0b:(arr==2)?Whh1f:Whh1b;
            bf16* dst = (arr==0)?d_Wh0f:(arr==1)?d_Wh0b:(arr==2)?d_Wh1f:d_Wh1b;
            dst[jj] = __float2bfloat16_rn(src[sr*512 + k]);
        } else if (i < e4){
            int np = i - e3;
            int np2 = np & 2047;
            int sr = (np2 & 3)*512 + (np2 >> 2);
            d_b0m[np] = (np < 2048) ? (bih0f[sr] + bhh0f[sr]) : (bih0b[sr] + bhh0b[sr]);
        } else if (i < e5){
            int np = i - e4;
            int np2 = np & 2047;
            int sr = (np2 & 3)*512 + (np2 >> 2);
            d_b1m[np] = (np < 2048) ? (bih1f[sr] + bhh1f[sr]) : (bih1b[sr] + bhh1b[sr]);
        } else if (i < e6){
            int j = i - e5;
            d_fc2wB[j] = __float2bfloat16_rn(fc2w[j]);
        } else if (i < e7){
            int j = i - e6;
            d_fc3wB[j] = __float2bfloat16_rn(fc3w[j]);
        } else {
            ((int*)d_slot)[i - e7] = 0;
        }
    }
}

// fold BN into fc1
__global__ void prep_fc(const float* __restrict__ fc1w, const float* __restrict__ fc1b,
                        const float* __restrict__ gamma, const float* __restrict__ beta,
                        const float* __restrict__ mean, const float* __restrict__ var)
{
    __shared__ float red[256];
    int r = blockIdx.x;
    int tid = threadIdx.x;
    float part = 0.f;
    for (int c = tid; c < 1024; c += 256){
        float sc = gamma[c] * rsqrtf(var[c] + 1e-5f);
        float tc = beta[c] - mean[c]*sc;
        float w = fc1w[r*1024 + c];
        d_fc1wP[r*1024 + c] = __float2bfloat16_rn(w * sc);
        part += w * tc;
    }
    red[tid] = part;
    __syncthreads();
    for (int off = 128; off > 0; off >>= 1){
        if (tid < off) red[tid] += red[tid + off];
        __syncthreads();
    }
    if (tid == 0) d_fc1bP[r] = fc1b[r] + red[0];
}

// ------------------- bf16 GEMM (ldmatrix, 3-stage pipeline) -------------------
#define BRS 40
#define GBUFE (2*128*BRS)          // elems per full stage buffer (A+B)
__global__ __launch_bounds__(256) void gemm_bf16(
    const bf16* __restrict__ A, const bf16* __restrict__ W,
    const float* __restrict__ bias, void* __restrict__ Cv,
    int M, int N, int K, int relu, int outBf)
{
    extern __shared__ bf16 smb[];
    int tid  = threadIdx.x;
    int warp = tid >> 5, lane = tid & 31;
    int wm = warp >> 2, wn = warp & 3;
    int g = lane >> 2, tg = lane & 3;
    int m0 = blockIdx.y*128, n0 = blockIdx.x*128;

    float acc[4][4][4];
#pragma unroll
    for (int a = 0; a < 4; a++)
#pragma unroll
        for (int b = 0; b < 4; b++)
#pragma unroll
            for (int c = 0; c < 4; c++) acc[a][b][c] = 0.f;

    int KT = K >> 5;

    auto stage = [&](int kt, int bb){
        bf16* As = smb + bb*GBUFE;
        bf16* Bs = As + 128*BRS;
        const bf16* Ag = A + (size_t)m0*K + kt*32;
#pragma unroll
        for (int i = 0; i < 2; i++){
            int q = i*256 + tid;
            int r = q >> 2;
            int c = (q & 3) * 8;
            cp16(&As[r*BRS + c], Ag + (size_t)r*K + c);
        }
        const bf16* Wg = W + kt*32;
#pragma unroll
        for (int i = 0; i < 2; i++){
            int q = i*256 + tid;
            int r = q >> 2;
            int c = (q & 3) * 8;
            int nr = n0 + r;
            int nc = nr < N ? nr : 0;
            cp16z(&Bs[r*BRS + c], Wg + (size_t)nc*K + c, nr < N);
        }
        cp_commit();
    };

    stage(0, 0);
    if (KT > 1) stage(1, 1);
    if (KT > 2) stage(2, 2);

    // ldmatrix lane addressing
    int lrow = lane & 15;
    int lcol = (lane >> 4) * 16;
    unsigned Sbase = (unsigned)__cvta_generic_to_shared(smb);
    const unsigned BUFB = (unsigned)GBUFE*2u;     // bytes per stage buffer
    unsigned aW = (unsigned)((wm*64 + lrow)*BRS)*2u + lcol;
    unsigned bW = (unsigned)(128*BRS)*2u + (unsigned)((wn*32 + lrow)*BRS)*2u + lcol;

    for (int kt = 0; kt < KT; kt++){
        if (kt < KT-2) cp_wait2();
        else if (kt == KT-2) cp_wait1();
        else cp_wait0();
        __syncthreads();
        int bb = kt % 3;
        unsigned aAd = Sbase + (unsigned)bb*BUFB + aW;
        unsigned bAd = Sbase + (unsigned)bb*BUFB + bW;
#pragma unroll
        for (int kk = 0; kk < 2; kk++){
            unsigned ko = (unsigned)kk * 32u;
            unsigned af[4][4];
#pragma unroll
            for (int mt = 0; mt < 4; mt++)
                ldsm4(af[mt][0], af[mt][1], af[mt][2], af[mt][3],
                      aAd + (unsigned)(mt*16*BRS)*2u + ko);
            unsigned b0,b1,b2,b3, c0,c1,c2,c3;
            ldsm4(b0,b1,b2,b3, bAd + ko);
            ldsm4(c0,c1,c2,c3, bAd + (unsigned)(16*BRS)*2u + ko);
#pragma unroll
            for (int mt = 0; mt < 4; mt++){
                mma16r(acc[mt][0], af[mt][0], af[mt][1], af[mt][2], af[mt][3], b0, b2);
                mma16r(acc[mt][1], af[mt][0], af[mt][1], af[mt][2], af[mt][3], b1, b3);
                mma16r(acc[mt][2], af[mt][0], af[mt][1], af[mt][2], af[mt][3], c0, c2);
                mma16r(acc[mt][3], af[mt][0], af[mt][1], af[mt][2], af[mt][3], c1, c3);
            }
        }
        __syncthreads();
        if (kt + 3 < KT) stage(kt+3, bb);
    }

#pragma unroll
    for (int mt = 0; mt < 4; mt++){
        int row = m0 + wm*64 + mt*16 + g;
#pragma unroll
        for (int nt = 0; nt < 4; nt++){
            int col = n0 + wn*32 + nt*8 + 2*tg;
            if (col < N){
                float b0 = bias[col], b1 = bias[col+1];
                float v0 = acc[mt][nt][0] + b0;
                float v1 = acc[mt][nt][1] + b1;
                float v2 = acc[mt][nt][2] + b0;
                float v3 = acc[mt][nt][3] + b1;
                if (relu){
                    v0 = fmaxf(v0, 0.f); v1 = fmaxf(v1, 0.f);
                    v2 = fmaxf(v2, 0.f); v3 = fmaxf(v3, 0.f);
                }
                if (outBf){
                    bf16* C16 = (bf16*)Cv;
                    *(bf162*)&C16[(size_t)row*N + col]     = __floats2bfloat162_rn(v0, v1);
                    *(bf162*)&C16[(size_t)(row+8)*N + col] = __floats2bfloat162_rn(v2, v3);
                } else {
                    float* C = (float*)Cv;
                    *(float2*)&C[(size_t)row*N + col]     = make_float2(v0, v1);
                    *(float2*)&C[(size_t)(row+8)*N + col] = make_float2(v2, v3);
                }
            }
        }
    }
}

// ------------------- persistent bidirectional LSTM layer (R13/R14) -------------------
#define WSB 520
__global__ __launch_bounds__(256) void lstm_layer(
    const bf16* __restrict__ pre,
    const bf16* __restrict__ whhF, const bf16* __restrict__ whhB,
    bf16* __restrict__ out, int gen0)
{
    extern __shared__ char smraw[];
    bf16* whh_s = (bf16*)smraw;                  // [32][WSB]
    bf16* h_s   = whh_s + 32*WSB;                // [64][WSB]
    bf16* pre_s = h_s + 64*WSB;                  // [2][64][32]
    float* G_s  = (float*)(pre_s + 2*64*32);     // [64][36]
    float* c_s  = G_s + 64*36;                   // [64][8]

    int tid = threadIdx.x;
    int warp = tid >> 5, lane = tid & 31;
    int wm = warp >> 1, wn = warp & 1;
    int g = lane >> 2, tg = lane & 3;
    int dir = blockIdx.x >> 6;
    int ns  = blockIdx.x & 63;
    int n0  = ns*32;
    int j0  = ns*8;
    const bf16* whh = dir ? whhB : whhF;
    int* slots = &d_slot[dir][0];

#pragma unroll
    for (int i = 0; i < 8; i++){
        int q = i*256 + tid;
        int r = q >> 6;
        int c = (q & 63) * 8;
        cp16(&whh_s[r*WSB + c], &whh[(n0 + r)*512 + c]);
    }
    cp_commit();
    for (int q = tid; q < 64*8; q += 256) c_s[q] = 0.f;
    cp_wait0();
    __syncthreads();

    int lrow = lane & 15;
    int lcol = (lane >> 4) * 16;
    unsigned hbase = (unsigned)__cvta_generic_to_shared(h_s);
    unsigned wbase = (unsigned)__cvta_generic_to_shared(whh_s);
    unsigned aAddr = hbase + (unsigned)((wm*16 + lrow)*WSB)*2u + lcol;
    unsigned bAddr = wbase + (unsigned)((wn*16 + lrow)*WSB)*2u + lcol;

    unsigned br[32][4];
#pragma unroll
    for (int k16 = 0; k16 < 32; k16++)
        ldsm4(br[k16][0], br[k16][1], br[k16][2], br[k16][3], bAddr + (unsigned)k16*32u);

    int ub = tid >> 2;
    int uu = (tid & 3)*2;
    int pr_ = tid >> 2, pc_ = (tid & 3)*8;

    {
        int t0 = dir ? (SEQ-1) : 0;
        cp16(&pre_s[pr_*32 + pc_], &pre[((size_t)(pr_*SEQ + t0))*4096 + dir*2048 + n0 + pc_]);
        cp_commit();
    }

    for (int s = 0; s < SEQ; s++){
        int t  = dir ? (SEQ-1 - s) : s;
        int rp = s & 1;
        int wp = rp ^ 1;

        if (s > 0){
            const bf16* hsrc = d_hbuf + (size_t)(rp*2 + dir)*BATCH*HID;
#pragma unroll
            for (int i = 0; i < 8; i++){
                int q = i*256 + tid;
                int r = q >> 5;
                int c = (q & 31) * 8;
                cp16(&h_s[r*WSB + c], &hsrc[r*HID + c]);
            }
            cp_commit();
#pragma unroll
            for (int i = 0; i < 8; i++){
                int q = i*256 + tid;
                int r = q >> 5;
                int c = (q & 31) * 8 + 256;
                cp16(&h_s[r*WSB + c], &hsrc[r*HID + c]);
            }
            cp_commit();
        }
        {
            int sn = s + 1;
            if (sn < SEQ){
                int tn = dir ? (SEQ-1 - sn) : sn;
                bf16* pb = pre_s + (sn & 1)*2048;
                cp16(&pb[pr_*32 + pc_], &pre[((size_t)(pr_*SEQ + tn))*4096 + dir*2048 + n0 + pc_]);
            }
            cp_commit();
        }

        float acc[2][4];
#pragma unroll
        for (int b = 0; b < 2; b++)
#pragma unroll
            for (int c = 0; c < 4; c++) acc[b][c] = 0.f;

        if (s > 0){
            cp_wait2();
            __syncthreads();
#pragma unroll
            for (int k16 = 0; k16 < 16; k16++){
                unsigned off = (unsigned)k16 * 32u;
                unsigned a0,a1,a2,a3;
                ldsm4(a0,a1,a2,a3, aAddr + off);
                mma16r(acc[0], a0,a1,a2,a3, br[k16][0], br[k16][2]);
                mma16r(acc[1], a0,a1,a2,a3, br[k16][1], br[k16][3]);
            }
            cp_wait1();
            __syncthreads();
#pragma unroll
            for (int k16 = 16; k16 < 32; k16++){
                unsigned off = (unsigned)k16 * 32u;
                unsigned a0,a1,a2,a3;
                ldsm4(a0,a1,a2,a3, aAddr + off);
                mma16r(acc[0], a0,a1,a2,a3, br[k16][0], br[k16][2]);
                mma16r(acc[1], a0,a1,a2,a3, br[k16][1], br[k16][3]);
            }
        } else {
            cp_wait1();
        }

        {
            int rr = wm*16 + g;
#pragma unroll
            for (int nt = 0; nt < 2; nt++){
                int cc = wn*16 + nt*8 + 2*tg;
                G_s[rr*36 + cc]        = acc[nt][0];
                G_s[rr*36 + cc + 1]    = acc[nt][1];
                G_s[(rr+8)*36 + cc]    = acc[nt][2];
                G_s[(rr+8)*36 + cc+1]  = acc[nt][3];
            }
        }
        __syncthreads();

        unsigned pk;
        {
            const bf16* pcur = pre_s + (s & 1)*2048;
            bf16* hdst = d_hbuf + (size_t)(wp*2 + dir)*BATCH*HID;
            float hv2[2];
#pragma unroll
            for (int k = 0; k < 2; k++){
                int u = uu + k;
                float4 Gv = *(float4*)&G_s[ub*36 + 4*u];
                bf162 pA = *(bf162*)&pcur[ub*32 + 4*u];
                bf162 pB = *(bf162*)&pcur[ub*32 + 4*u + 2];
                float iv = Gv.x + __low2float(pA);
                float fv = Gv.y + __high2float(pA);
                float gv = Gv.z + __low2float(pB);
                float ov = Gv.w + __high2float(pB);
                float co = c_s[ub*8 + u];
                float cn = fsig(fv)*co + fsig(iv)*ftanh(gv);
                hv2[k] = fsig(ov)*ftanh(cn);
                c_s[ub*8 + u] = cn;
            }
            bf162 p0 = __floats2bfloat162_rn(hv2[0], hv2[1]);
            pk = *(unsigned*)&p0;
            *(unsigned*)&hdst[ub*HID + j0 + uu] = pk;
        }

        __syncthreads();
        int target = gen0 + s + 1;
        if (tid == 0) st_release(&slots[ns*32], target);
        *(unsigned*)&out[(size_t)(ub*SEQ + t)*H2 + dir*HID + j0 + uu] = pk;
        if (tid < 64){
            while (ld_acquire(&slots[tid*32]) < target) { }
        }
        __syncthreads();
    }
}

// ------------------- CRF: 1 sync/step, stale-common-ref logsumexp -------------------
__global__ void crf_kernel(const float* __restrict__ em, const int* __restrict__ tags,
                           const float* __restrict__ start, const float* __restrict__ endv,
                           const float* __restrict__ trans, float* __restrict__ v)
{
    __shared__ float E[NTAG*49];
    __shared__ float pbuf[2][NTAG];
    __shared__ float a0s[2];
    __shared__ float red[64];
    __shared__ float alf[NTAG];
    __shared__ float num_s;
    int b = blockIdx.x;
    int tid = threadIdx.x;
    const int* tg = tags + b*SEQ;
    const float* eb = em + b*SEQ*NTAG;

    for (int q = tid; q < NTAG*NTAG; q += 64){
        int i = q / NTAG, j = q - i*NTAG;
        E[i*49 + j] = __expf(trans[q]);
    }
    float part = 0.f;
    for (int t = tid; t < SEQ; t += 64){
        int tt = tg[t];
        part += eb[t*NTAG + tt];
        if (t < SEQ-1) part += trans[tt*NTAG + tg[t+1]];
    }
    red[tid] = part;
    float al_r = 0.f;
    if (tid < NTAG) al_r = start[tid] + eb[tid];
    float ref = start[0] + eb[0];       // exact al[0] at t=0, common to all threads
    __syncthreads();
    if (tid == 0){
        float s = 0.f;
        for (int i = 0; i < 64; i++) s += red[i];
        num_s = s + start[tg[0]] + endv[tg[SEQ-1]];
    }
    __syncthreads();

    for (int t = 1; t < SEQ; t++){
        int cb = t & 1;
        if (tid < NTAG){
            pbuf[cb][tid] = __expf(al_r - ref);
            if (tid == 0) a0s[cb] = al_r;
        }
        __syncthreads();
        if (tid < NTAG){
            const float* pc = pbuf[cb];
            float ssum = 0.f;
#pragma unroll 8
            for (int i = 0; i < NTAG; i++) ssum += pc[i] * E[i*49 + tid];
            al_r = ref + __logf(ssum) + eb[t*NTAG + tid];
            ref = a0s[cb];              // al[0] at t-1: one-step-stale common ref (exact math)
        }
    }

    if (tid < NTAG) alf[tid] = al_r;
    __syncthreads();
    if (tid == 0){
        float m = -1e30f;
        for (int j = 0; j < NTAG; j++) m = fmaxf(m, alf[j] + endv[j]);
        float s = 0.f;
        for (int j = 0; j < NTAG; j++) s += __expf(alf[j] + endv[j] - m);
        v[b] = num_s - (m + __logf(s));
    }
}

__global__ void final_reduce(const float* __restrict__ v, float* __restrict__ out){
    __shared__ float s[64];
    s[threadIdx.x] = v[threadIdx.x];
    __syncthreads();
    if (threadIdx.x == 0){
        float a = 0.f;
        for (int i = 0; i < 64; i++) a += s[i];
        out[0] = -(a / 64.f);
    }
}

// ------------------- launch -------------------
extern "C" void kernel_launch(void* const* d_in, const int* in_sizes, int n_in,
                              void* d_out, int out_size)
{
    const float* inputs = (const float*)d_in[0];
    const int*   tags   = (const int*)d_in[1];
    const float *Wih0f=(const float*)d_in[2],  *Whh0f=(const float*)d_in[3],
                *bih0f=(const float*)d_in[4],  *bhh0f=(const float*)d_in[5];
    const float *Wih0b=(const float*)d_in[6],  *Whh0b=(const float*)d_in[7],
                *bih0b=(const float*)d_in[8],  *bhh0b=(const float*)d_in[9];
    const float *Wih1f=(const float*)d_in[10], *Whh1f=(const float*)d_in[11],
                *bih1f=(const float*)d_in[12], *bhh1f=(const float*)d_in[13];
    const float *Wih1b=(const float*)d_in[14], *Whh1b=(const float*)d_in[15],
                *bih1b=(const float*)d_in[16], *bhh1b=(const float*)d_in[17];
    const float *gamma=(const float*)d_in[18], *beta=(const float*)d_in[19],
                *mean=(const float*)d_in[20],  *var=(const float*)d_in[21];
    const float *fc1w=(const float*)d_in[22], *fc1b=(const float*)d_in[23];
    const float *fc2w=(const float*)d_in[24], *fc2b=(const float*)d_in[25];
    const float *fc3w=(const float*)d_in[26], *fc3b=(const float*)d_in[27];
    const float *crfS=(const float*)d_in[28], *crfE=(const float*)d_in[29],
                *crfT=(const float*)d_in[30];

    bf16 *pInb,*pW0m,*pW1m,*pWh0f,*pWh0b,*pWh1f,*pWh1b;
    bf16 *pFc1w,*pFc2w,*pFc3w,*pX1,*pX2,*pF1,*pF2,*pPre;
    float *pB0m,*pB1m,*pFc1b,*pEm,*pV;
    cudaGetSymbolAddress((void**)&pInb, d_inb);
    cudaGetSymbolAddress((void**)&pW0m, d_W0m);
    cudaGetSymbolAddress((void**)&pW1m, d_W1m);
    cudaGetSymbolAddress((void**)&pWh0f, d_Wh0f);
    cudaGetSymbolAddress((void**)&pWh0b, d_Wh0b);
    cudaGetSymbolAddress((void**)&pWh1f, d_Wh1f);
    cudaGetSymbolAddress((void**)&pWh1b, d_Wh1b);
    cudaGetSymbolAddress((void**)&pB0m, d_b0m);
    cudaGetSymbolAddress((void**)&pB1m, d_b1m);
    cudaGetSymbolAddress((void**)&pFc1w, d_fc1wP);
    cudaGetSymbolAddress((void**)&pFc1b, d_fc1bP);
    cudaGetSymbolAddress((void**)&pFc2w, d_fc2wB);
    cudaGetSymbolAddress((void**)&pFc3w, d_fc3wB);
    cudaGetSymbolAddress((void**)&pPre, d_pre);
    cudaGetSymbolAddress((void**)&pX1, d_x1);
    cudaGetSymbolAddress((void**)&pX2, d_x2);
    cudaGetSymbolAddress((void**)&pF1, d_f1);
    cudaGetSymbolAddress((void**)&pF2, d_f2);
    cudaGetSymbolAddress((void**)&pEm, d_em);
    cudaGetSymbolAddress((void**)&pV, d_v);

    const int gemm_smem = 3*GBUFE*2;
    const int lstm_smem = (32*WSB + 64*WSB + 2*64*32)*2 + (64*36 + 64*8)*4;
    cudaFuncSetAttribute(gemm_bf16, cudaFuncAttributeMaxDynamicSharedMemorySize, gemm_smem);
    cudaFuncSetAttribute(lstm_layer, cudaFuncAttributeMaxDynamicSharedMemorySize, lstm_smem);

    prep_all<<<2048,256>>>(inputs, Wih0f, Wih0b, Whh0f, Whh0b, Wih1f, Wih1b, Whh1f, Whh1b,
                           bih0f, bhh0f, bih0b, bhh0b, bih1f, bhh1f, bih1b, bhh1b,
                           fc2w, fc3w);
    prep_fc<<<512,256>>>(fc1w, fc1b, gamma, beta, mean, var);
    gemm_bf16<<<dim3(32,128),256,gemm_smem>>>(pInb, pW0m, pB0m, pPre, MROWS, 4096, 256, 0, 1);
    lstm_layer<<<128,256,lstm_smem>>>(pPre, pWh0f, pWh0b, pX1, 0);
    gemm_bf16<<<dim3(32,128),256,gemm_smem>>>(pX1, pW1m, pB1m, pPre, MROWS, 4096, 1024, 0, 1);
    lstm_layer<<<128,256,lstm_smem>>>(pPre, pWh1f, pWh1b, pX2, 256);
    gemm_bf16<<<dim3(4,128),256,gemm_smem>>>(pX2, pFc1w, pFc1b, pF1, MROWS, 512, 1024, 1, 1);
    gemm_bf16<<<dim3(2,128),256,gemm_smem>>>(pF1, pFc2w, fc2b, pF2, MROWS, 256, 512, 1, 1);
    gemm_bf16<<<dim3(1,128),256,gemm_smem>>>(pF2, pFc3w, fc3b, pEm, MROWS, NTAG, 256, 0, 0);
    crf_kernel<<<64,64>>>(pEm, tags, crfS, crfE, crfT, pV);
    final_reduce<<<1,64>>>(pV, (float*)d_out);
}